// round 15
// baseline (speedup 1.0000x reference)
#include <cuda_runtime.h>
#include <cuda_fp16.h>
#include <cstdint>
#include <math.h>

// ---------------- problem constants ----------------
constexpr int cB = 16, cT = 1024, cD = 256, cH = 2, cDK = 64, cC = 1024;
constexpr int cNT = cB * cT;            // 16384 tokens
constexpr long cTT = (long)cT * cT;     // 1M
constexpr float LN_EPS = 1e-5f;

// ---------------- device scratch (no allocs allowed) ----------------
__device__ float g_apre[cNT * cD];
__device__ float g_a   [cNT * cD];
__device__ float g_o2 [cNT * cD];
__device__ float g_dwn[cB * 9];
__device__ float g_pwn[cB * cC];        // sum of squares (atomic); inv-norm applied inline in pt epilogue
__device__ float g_bqkv[384];
// fp16 buffers
__device__ __half g_xh  [cNT * cD];
__device__ __half g_xl  [cNT * cD];
__device__ __half g_qkvh[cNT * 384];
__device__ __half g_qkvl[cNT * 384];
__device__ __half g_vTh [(long)cB * cH * 64 * cT];    // compact 64 rows per (b,h)
__device__ __half g_atth[(long)cB * cH * cTT];
__device__ __half g_ctxh[cNT * 128];
__device__ __half g_ctxl[cNT * 128];
__device__ __half g_ah  [cNT * cD];
__device__ __half g_hh  [cNT * cC];
__device__ __half g_deph[cNT * cC];
__device__ __half g_pth [cNT * cC];
__device__ __half g_pwT [(long)cB * cC * cC];
__device__ __half g_w1  [cC * cD];
__device__ __half g_w2  [cD * cC];
__device__ __half g_wqkv [384 * cD];
__device__ __half g_wqkvl[384 * cD];
__device__ __half g_wo  [cD * 128];
__device__ __half g_wol [cD * 128];

// ---------------- helpers ----------------
__device__ __forceinline__ uint32_t smem_u32(const void* p) {
    uint32_t a;
    asm("{ .reg .u64 t; cvta.to.shared.u64 t, %1; cvt.u32.u64 %0, t; }" : "=r"(a) : "l"(p));
    return a;
}
#define SW128(off) ((off) ^ (((off) >> 3) & 0x70))

__device__ __forceinline__ void split_h(float v, __half& h, __half& l) {
    h = __float2half_rn(v);
    l = __float2half_rn(v - __half2float(h));
}

__device__ __forceinline__ void ldsm4(uint32_t* r, uint32_t addr) {
    asm volatile("ldmatrix.sync.aligned.m8n8.x4.shared.b16 {%0,%1,%2,%3}, [%4];"
        : "=r"(r[0]), "=r"(r[1]), "=r"(r[2]), "=r"(r[3]) : "r"(addr));
}
__device__ __forceinline__ void mma16816(float* d, const uint32_t* a, const uint32_t* b) {
    asm volatile("mma.sync.aligned.m16n8k16.row.col.f32.f16.f16.f32 "
        "{%0,%1,%2,%3}, {%4,%5,%6,%7}, {%8,%9}, {%0,%1,%2,%3};"
        : "+f"(d[0]), "+f"(d[1]), "+f"(d[2]), "+f"(d[3])
        : "r"(a[0]), "r"(a[1]), "r"(a[2]), "r"(a[3]), "r"(b[0]), "r"(b[1]));
}
__device__ __forceinline__ void cp16(uint32_t saddr, const void* gptr) {
    asm volatile("cp.async.cg.shared.global [%0], [%1], 16;"
        :: "r"(saddr), "l"(__cvta_generic_to_global(gptr)));
}
__device__ __forceinline__ void cp_commit() {
    asm volatile("cp.async.commit_group;");
}
template<int N>
__device__ __forceinline__ void cp_wait() {
    asm volatile("cp.async.wait_group %0;" :: "n"(N));
}

__device__ __forceinline__ float warpReduceSum(float v) {
#pragma unroll
    for (int o = 16; o > 0; o >>= 1) v += __shfl_xor_sync(0xffffffffu, v, o);
    return v;
}
__device__ __forceinline__ float warpReduceMax(float v) {
#pragma unroll
    for (int o = 16; o > 0; o >>= 1) v = fmaxf(v, __shfl_xor_sync(0xffffffffu, v, o));
    return v;
}

// ---------------- mma.sync fp16 GEMM body ----------------
// D[M,N] = A[M,K] @ B[N,K]^T.  Tile 128 x BN (BN=128 or 64), BK=64.
// NPROD=1: A,B single fp16 (3-stage, single barrier per chunk).
// NPROD=3: A and B split (2-stage, two barriers per chunk).
// EPI: 2 = +bias[n]+aux residual -> f32 | 5 = acc*0.125 -> f32
//      6 = +bias -> fp16 split | 8 = raw -> fp16 split
//      9 = mish(acc+bias) -> fp16 single
//      10 = acc * invnorm(aux[n]) + bias[n] -> fp16 single   (aux = raw sum of squares)
constexpr int MM_SMEM1  = 3 * 32768 + 1024;            // 1-prod, BN=128, 3 stages
constexpr int MM_SMEM1N = 3 * 24576 + 1024;            // 1-prod, BN=64,  3 stages
constexpr int MM_SMEM3  = 2 * 65536 + 1024;            // 3-prod, BN=128, 2 stages
constexpr int MM_SMEM3S = 1 * 65536 + 1024;            // 3-prod, BN=128, nk=1 (scores)

template<int EPI, int NPROD, int BN>
__device__ __forceinline__ void mma_body(
    const __half* __restrict__ Ah, const __half* __restrict__ Al,
    const __half* __restrict__ Bh, const __half* __restrict__ Bl,
    float* __restrict__ C, __half* __restrict__ Ch, __half* __restrict__ Cl,
    int Kd, int lda, int ldb, int ldc, int nLim, int zdiv,
    long aQ, long aR, long bQ, long bR, long cQ, long cR,
    long biasZ, long auxZ,
    const float* __restrict__ bias, const float* __restrict__ aux)
{
    constexpr int ASZ  = 16384;            // 128 rows x 64 cols fp16
    constexpr int BSZ  = BN * 128;
    constexpr int NAt  = (NPROD >= 2) ? 2 : 1;
    constexpr int NBt  = (NPROD == 3) ? 2 : 1;
    constexpr int BOFF = NAt * ASZ;
    constexpr int STAGE = NAt * ASZ + NBt * BSZ;
    constexpr int NSTG  = (NPROD == 1) ? 3 : 2;
    constexpr int NBT   = BN / 32;         // 16-col subtiles per warp-half (4 or 2)
    extern __shared__ char sm_raw[];
    uint32_t sb0 = smem_u32(sm_raw);
    uint32_t sb  = (sb0 + 1023u) & ~1023u;

    int z = blockIdx.z;
    int zq = z / zdiv, zr = z - zq * zdiv;
    long aoff = (long)zq * aQ + (long)zr * aR;
    long boff = (long)zq * bQ + (long)zr * bR;
    long coff = (long)zq * cQ + (long)zr * cR;
    Ah += aoff;
    if (NPROD >= 2) Al += aoff;
    Bh += boff;
    if (NPROD == 3) Bl += boff;
    if (C)  C  += coff;
    if (Ch) Ch += coff;
    if (Cl) Cl += coff;
    const float* biasp = bias ? bias + (long)zq * biasZ : nullptr;
    const float* auxp  = aux  ? aux  + (long)zq * auxZ  : nullptr;

    int m0 = blockIdx.y * 128, n0 = blockIdx.x * BN;
    int tid = threadIdx.x, wid = tid >> 5, lane = tid & 31;
    int wm = wid & 3, wn = wid >> 2;

    int lrow = tid >> 3, lcq = tid & 7;

    auto issue_stage = [&](int k0, uint32_t sbase) {
#pragma unroll
        for (int ti = 0; ti < 4; ti++) {
            int row = lrow + ti * 32;
            uint32_t soff = SW128((uint32_t)(row * 128 + lcq * 16));
            long ga = (long)(m0 + row) * lda + k0 + lcq * 8;
            cp16(sbase + soff, Ah + ga);
            if (NPROD >= 2) cp16(sbase + ASZ + soff, Al + ga);
        }
#pragma unroll
        for (int ti = 0; ti < BN / 32; ti++) {
            int row = lrow + ti * 32;
            uint32_t soff = SW128((uint32_t)(row * 128 + lcq * 16));
            long gb = (long)(n0 + row) * ldb + k0 + lcq * 8;
            cp16(sbase + BOFF + soff, Bh + gb);
            if (NPROD == 3) cp16(sbase + BOFF + BSZ + soff, Bl + gb);
        }
        cp_commit();
    };

    float acc[2][BN / 16][4];
#pragma unroll
    for (int i = 0; i < 2; i++)
#pragma unroll
        for (int j = 0; j < BN / 16; j++)
#pragma unroll
            for (int l = 0; l < 4; l++) acc[i][j][l] = 0.f;

    auto compute_chunk = [&](uint32_t cur) {
        uint32_t uAh = cur, uAl = cur + ASZ, uBh = cur + BOFF, uBl = cur + BOFF + BSZ;
#pragma unroll
        for (int ks = 0; ks < 4; ks++) {
            uint32_t afh[2][4], afl[2][4], bfh[NBT][4], bfl[NBT][4];
#pragma unroll
            for (int mt = 0; mt < 2; mt++) {
                int r = wm * 32 + mt * 16 + (lane & 15);
                int kc = ks * 2 + (lane >> 4);
                uint32_t off = SW128((uint32_t)(r * 128 + kc * 16));
                ldsm4(afh[mt], uAh + off);
                if (NPROD >= 2) ldsm4(afl[mt], uAl + off);
            }
#pragma unroll
            for (int bt = 0; bt < NBT; bt++) {
                int r = wn * (BN / 2) + bt * 16 + (lane & 7) + ((lane >> 4) << 3);
                int kc = ks * 2 + ((lane >> 3) & 1);
                uint32_t off = SW128((uint32_t)(r * 128 + kc * 16));
                ldsm4(bfh[bt], uBh + off);
                if (NPROD == 3) ldsm4(bfl[bt], uBl + off);
            }
#pragma unroll
            for (int p = 0; p < NPROD; p++)
#pragma unroll
                for (int mt = 0; mt < 2; mt++)
#pragma unroll
                    for (int bt = 0; bt < NBT; bt++)
#pragma unroll
                        for (int hh = 0; hh < 2; hh++) {
                            const uint32_t* af  = (p == 1) ? afl[mt] : afh[mt];
                            const uint32_t* bfp = (p == 2) ? &bfl[bt][hh * 2] : &bfh[bt][hh * 2];
                            mma16816(acc[mt][bt * 2 + hh], af, bfp);
                        }
        }
    };

    int nk = Kd >> 6;
#pragma unroll
    for (int s = 0; s < NSTG - 1; s++)
        if (s < nk) issue_stage(s << 6, sb + (uint32_t)s * STAGE);

    if (NSTG == 3) {
        // 3-stage: single barrier per chunk. Stage written at iter i ((i+2)%3)
        // was last read at iter i-1; passing this iter's barrier guarantees all
        // warps finished those reads, so no trailing barrier is needed.
        for (int i = 0; i < nk; i++) {
            uint32_t cur = sb + (uint32_t)(i % 3) * STAGE;
            if (nk - 1 - i >= 1) cp_wait<1>();
            else                 cp_wait<0>();
            __syncthreads();
            int j = i + 2;
            if (j < nk) issue_stage(j << 6, sb + (uint32_t)(j % 3) * STAGE);
            compute_chunk(cur);
        }
    } else {
        for (int i = 0; i < nk; i++) {
            uint32_t cur = sb + (uint32_t)(i & 1) * STAGE;
            int j = i + 1;
            if (j < nk) {
                issue_stage(j << 6, sb + (uint32_t)(j & 1) * STAGE);
                cp_wait<1>();
            } else {
                cp_wait<0>();
            }
            __syncthreads();
            compute_chunk(cur);
            __syncthreads();
        }
    }

    // epilogue
#pragma unroll
    for (int mt = 0; mt < 2; mt++)
#pragma unroll
        for (int bt = 0; bt < NBT; bt++)
#pragma unroll
            for (int hh = 0; hh < 2; hh++) {
                float* d = acc[mt][bt * 2 + hh];
                int col = n0 + wn * (BN / 2) + bt * 16 + hh * 8 + (lane & 3) * 2;
                int r0  = m0 + wm * 32 + mt * 16 + (lane >> 2);
                if (col >= nLim) continue;
#pragma unroll
                for (int half = 0; half < 2; half++) {
                    int row = r0 + half * 8;
                    float t0 = d[half * 2 + 0], t1 = d[half * 2 + 1];
                    if (EPI == 2) {
                        t0 += biasp[col]     + auxp[(long)row * ldc + col];
                        t1 += biasp[col + 1] + auxp[(long)row * ldc + col + 1];
                        float2 v = {t0, t1};
                        *reinterpret_cast<float2*>(C + (long)row * ldc + col) = v;
                    } else if (EPI == 5) {
                        float2 v = {t0 * 0.125f, t1 * 0.125f};
                        *reinterpret_cast<float2*>(C + (long)row * ldc + col) = v;
                    } else if (EPI == 9) {
                        t0 += biasp[col];
                        t1 += biasp[col + 1];
                        float sp0 = (t0 > 20.f) ? t0 : log1pf(expf(t0));
                        float sp1 = (t1 > 20.f) ? t1 : log1pf(expf(t1));
                        t0 = t0 * tanhf(sp0);
                        t1 = t1 * tanhf(sp1);
                        __half2 hv = {__float2half_rn(t0), __float2half_rn(t1)};
                        *reinterpret_cast<__half2*>(Ch + (long)row * ldc + col) = hv;
                    } else if (EPI == 10) {
                        float inv0 = 1.f / fmaxf(sqrtf(auxp[col]),     1e-12f);
                        float inv1 = 1.f / fmaxf(sqrtf(auxp[col + 1]), 1e-12f);
                        t0 = t0 * inv0 + biasp[col];
                        t1 = t1 * inv1 + biasp[col + 1];
                        __half2 hv = {__float2half_rn(t0), __float2half_rn(t1)};
                        *reinterpret_cast<__half2*>(Ch + (long)row * ldc + col) = hv;
                    } else { // 6, 8: fp16 split outputs
                        if (EPI == 6) {
                            t0 += biasp[col];
                            t1 += biasp[col + 1];
                        }
                        __half h0, l0, h1, l1;
                        split_h(t0, h0, l0);
                        split_h(t1, h1, l1);
                        __half2 hv = {h0, h1}, lv = {l0, l1};
                        *reinterpret_cast<__half2*>(Ch + (long)row * ldc + col) = hv;
                        *reinterpret_cast<__half2*>(Cl + (long)row * ldc + col) = lv;
                    }
                }
            }
}

template<int EPI>
__global__ void __launch_bounds__(256, 2) mma_gemm1(
    const __half* __restrict__ Ah, const __half* __restrict__ Bh,
    float* __restrict__ C, __half* __restrict__ Ch,
    int Kd, int lda, int ldb, int ldc, int nLim, int zdiv,
    long aQ, long aR, long bQ, long bR, long cQ, long cR,
    long biasZ, long auxZ,
    const float* __restrict__ bias, const float* __restrict__ aux)
{
    mma_body<EPI, 1, 128>(Ah, nullptr, Bh, nullptr, C, Ch, nullptr, Kd, lda, ldb, ldc, nLim, zdiv,
                          aQ, aR, bQ, bR, cQ, cR, biasZ, auxZ, bias, aux);
}

// 1-product, BN=64, split fp16 output (for ctx)
template<int EPI>
__global__ void __launch_bounds__(256, 2) mma_gemm1s(
    const __half* __restrict__ Ah, const __half* __restrict__ Bh,
    __half* __restrict__ Ch, __half* __restrict__ Cl,
    int Kd, int lda, int ldb, int ldc, int nLim, int zdiv,
    long aQ, long aR, long bQ, long bR, long cQ, long cR)
{
    mma_body<EPI, 1, 64>(Ah, nullptr, Bh, nullptr, nullptr, Ch, Cl, Kd, lda, ldb, ldc, nLim, zdiv,
                         aQ, aR, bQ, bR, cQ, cR, 0, 0, nullptr, nullptr);
}

template<int EPI>
__global__ void __launch_bounds__(256) mma_gemm3(
    const __half* __restrict__ Ah, const __half* __restrict__ Al,
    const __half* __restrict__ Bh, const __half* __restrict__ Bl,
    float* __restrict__ C, __half* __restrict__ Ch, __half* __restrict__ Cl,
    int Kd, int lda, int ldb, int ldc, int nLim, int zdiv,
    long aQ, long aR, long bQ, long bR, long cQ, long cR,
    long biasZ, long auxZ,
    const float* __restrict__ bias, const float* __restrict__ aux)
{
    mma_body<EPI, 3, 128>(Ah, Al, Bh, Bl, C, Ch, Cl, Kd, lda, ldb, ldc, nLim, zdiv,
                          aQ, aR, bQ, bR, cQ, cR, biasZ, auxZ, bias, aux);
}

// scores-specific: reg-capped for 2 CTAs/SM, launched with 1-stage smem (nk=1)
template<int EPI>
__global__ void __launch_bounds__(256, 2) mma_gemm3sc(
    const __half* __restrict__ Ah, const __half* __restrict__ Al,
    const __half* __restrict__ Bh, const __half* __restrict__ Bl,
    float* __restrict__ C,
    int Kd, int lda, int ldb, int ldc, int nLim, int zdiv,
    long aQ, long aR, long bQ, long bR, long cQ, long cR)
{
    mma_body<EPI, 3, 128>(Ah, Al, Bh, Bl, C, nullptr, nullptr, Kd, lda, ldb, ldc, nLim, zdiv,
                          aQ, aR, bQ, bR, cQ, cR, 0, 0, nullptr, nullptr);
}

// ---------------- softmax (in place; emits fp16 single; vectorized) ----------------
__global__ void __launch_bounds__(256) softmax_k(float* __restrict__ attn,
                                                 const unsigned char* __restrict__ smask,
                                                 __half* __restrict__ ath)
{
    int i = blockIdx.x, h = blockIdx.y, b = blockIdx.z;
    long rbase = (((long)(b * cH + h)) * cT + i) * cT;
    float* row = attn + rbase;
    const unsigned char* mrow = smask + ((long)b * cT + i) * cT;
    int tid = threadIdx.x, lane = tid & 31, wid = tid >> 5;
    __shared__ float red[8];
    __shared__ float bc;

    float4 v4 = *reinterpret_cast<const float4*>(row + tid * 4);
    uchar4 m4 = *reinterpret_cast<const uchar4*>(mrow + tid * 4);
    float v[4] = {v4.x, v4.y, v4.z, v4.w};
    if (m4.x) v[0] = -1e9f;
    if (m4.y) v[1] = -1e9f;
    if (m4.z) v[2] = -1e9f;
    if (m4.w) v[3] = -1e9f;
    float mx = fmaxf(fmaxf(v[0], v[1]), fmaxf(v[2], v[3]));
    mx = warpReduceMax(mx);
    if (lane == 0) red[wid] = mx;
    __syncthreads();
    if (wid == 0) {
        float r = (lane < 8) ? red[lane] : -3.4e38f;
        r = warpReduceMax(r);
        if (lane == 0) bc = r;
    }
    __syncthreads();
    mx = bc;
    float sum = 0.f;
#pragma unroll
    for (int r = 0; r < 4; r++) { v[r] = expf(v[r] - mx); sum += v[r]; }
    __syncthreads();
    sum = warpReduceSum(sum);
    if (lane == 0) red[wid] = sum;
    __syncthreads();
    if (wid == 0) {
        float r = (lane < 8) ? red[lane] : 0.f;
        r = warpReduceSum(r);
        if (lane == 0) bc = r;
    }
    __syncthreads();
    float inv = 1.f / bc;
    float4 o = {v[0] * inv, v[1] * inv, v[2] * inv, v[3] * inv};
    *reinterpret_cast<float4*>(row + tid * 4) = o;
    __half2 h01 = {__float2half_rn(o.x), __float2half_rn(o.y)};
    __half2 h23 = {__float2half_rn(o.z), __float2half_rn(o.w)};
    *reinterpret_cast<__half2*>(ath + rbase + tid * 4)     = h01;
    *reinterpret_cast<__half2*>(ath + rbase + tid * 4 + 2) = h23;
}

// ---------------- LayerNorm over D=256; optional fp16 output ----------------
__global__ void __launch_bounds__(256) ln_k(const float* __restrict__ in,
                                            const float* __restrict__ g,
                                            const float* __restrict__ bta,
                                            const unsigned char* __restrict__ mask,
                                            float* __restrict__ out,
                                            __half* __restrict__ oh)
{
    long n = blockIdx.x;
    int tid = threadIdx.x, lane = tid & 31, wid = tid >> 5;
    __shared__ float red[8];
    __shared__ float stats[2];

    float x = in[n * cD + tid];
    float s = warpReduceSum(x);
    if (lane == 0) red[wid] = s;
    __syncthreads();
    if (wid == 0) {
        float r = (lane < 8) ? red[lane] : 0.f;
        r = warpReduceSum(r);
        if (lane == 0) stats[0] = r;
    }
    __syncthreads();
    float s2 = warpReduceSum(x * x);
    if (lane == 0) red[wid] = s2;
    __syncthreads();
    if (wid == 0) {
        float r = (lane < 8) ? red[lane] : 0.f;
        r = warpReduceSum(r);
        if (lane == 0) stats[1] = r;
    }
    __syncthreads();
    float mean = stats[0] * (1.f / cD);
    float var  = stats[1] * (1.f / cD) - mean * mean;
    float y = (x - mean) * rsqrtf(var + LN_EPS) * g[tid] + bta[tid];
    if (mask[n]) y = 0.f;
    out[n * cD + tid] = y;
    if (oh) oh[n * cD + tid] = __float2half_rn(y);
}

// ---------------- fused small weight prep (one launch) ----------------
// tasks (blockIdx.y): 0 Wq split, 1 Wk split, 2 Wv split, 3 Wo split,
//   4 w1 cvt, 5 w2 cvt, 6 bqkv pack + pwn-sum zero, 7 dwn (per-b block)
__device__ __forceinline__ void split4_at(const float* in, __half* oh, __half* ol, long i) {
    float4 v = *reinterpret_cast<const float4*>(in + i);
    __half h0, h1, h2, h3, l0, l1, l2, l3;
    split_h(v.x, h0, l0); split_h(v.y, h1, l1);
    split_h(v.z, h2, l2); split_h(v.w, h3, l3);
    __half2 ha = {h0, h1}, hb = {h2, h3}, la = {l0, l1}, lb = {l2, l3};
    *reinterpret_cast<__half2*>(oh + i)     = ha;
    *reinterpret_cast<__half2*>(oh + i + 2) = hb;
    *reinterpret_cast<__half2*>(ol + i)     = la;
    *reinterpret_cast<__half2*>(ol + i + 2) = lb;
}
__device__ __forceinline__ void cvt4_at(const float* in, __half* o, long i) {
    float4 v = *reinterpret_cast<const float4*>(in + i);
    __half2 a = {__float2half_rn(v.x), __float2half_rn(v.y)};
    __half2 b = {__float2half_rn(v.z), __float2half_rn(v.w)};
    *reinterpret_cast<__half2*>(o + i)     = a;
    *reinterpret_cast<__half2*>(o + i + 2) = b;
}

__global__ void __launch_bounds__(256) wprep_k(
    const float* __restrict__ Wq, const float* __restrict__ Wk,
    const float* __restrict__ Wv, const float* __restrict__ Wo,
    const float* __restrict__ w1, const float* __restrict__ w2,
    const float* __restrict__ bq, const float* __restrict__ bk,
    const float* __restrict__ bv,
    const float* __restrict__ d_w,
    __half* __restrict__ wqkvh, __half* __restrict__ wqkvl,
    __half* __restrict__ woh, __half* __restrict__ wol,
    __half* __restrict__ w1h, __half* __restrict__ w2h,
    float* __restrict__ bqkv, float* __restrict__ pwnsum,
    float* __restrict__ dwn)
{
    int task = blockIdx.y;
    long i = ((long)blockIdx.x * 256 + threadIdx.x) * 4;
    constexpr long SZp = (long)128 * cD;  // 32768
    constexpr long SZw = (long)cC * cD;   // 262144
    if (task == 0) { if (i < SZp) split4_at(Wq, wqkvh, wqkvl, i); }
    else if (task == 1) { if (i < SZp) split4_at(Wk, wqkvh + SZp, wqkvl + SZp, i); }
    else if (task == 2) { if (i < SZp) split4_at(Wv, wqkvh + 2 * SZp, wqkvl + 2 * SZp, i); }
    else if (task == 3) { if (i < SZp) split4_at(Wo, woh, wol, i); }
    else if (task == 4) { if (i < SZw) cvt4_at(w1, w1h, i); }
    else if (task == 5) { if (i < SZw) cvt4_at(w2, w2h, i); }
    else if (task == 6) {
        long t = (long)blockIdx.x * 256 + threadIdx.x;
        if (t < 128) bqkv[t] = bq[t];
        else if (t < 256) bqkv[t] = bk[t - 128];
        else if (t < 384) bqkv[t] = bv[t - 256];
        if (t < (long)cB * cC) pwnsum[t] = 0.f;
    } else { // 7: per-b depthwise weight inverse norms
        int b = blockIdx.x;
        if (b >= cB) return;
        int tid = threadIdx.x, lane = tid & 31;
        __shared__ float red9[9];
        if (tid < 9) red9[tid] = 0.f;
        __syncthreads();
        float s[9];
#pragma unroll
        for (int k = 0; k < 9; k++) s[k] = 0.f;
        for (int c = tid; c < cC; c += 256) {
            const float* wr = d_w + ((long)b * cC + c) * 9;
#pragma unroll
            for (int k = 0; k < 9; k++) { float w = wr[k]; s[k] += w * w; }
        }
#pragma unroll
        for (int k = 0; k < 9; k++) {
            float r = warpReduceSum(s[k]);
            if (lane == 0) atomicAdd(&red9[k], r);
        }
        __syncthreads();
        if (tid < 9)
            dwn[b * 9 + tid] = 1.f / fmaxf(sqrtf(red9[tid]), 1e-12f);
    }
}

// ---------------- fp32 -> fp16 hi/lo split (x) ----------------
__global__ void __launch_bounds__(256) cvt_split_h(const float* __restrict__ in,
                                                   __half* __restrict__ oh,
                                                   __half* __restrict__ ol, long n)
{
    long i = ((long)blockIdx.x * 256 + threadIdx.x) * 4;
    if (i >= n) return;
    split4_at(in, oh, ol, i);
}

// ---------------- qkv cols 256..383 (v) -> vT [(b,h)][n(64)][t] fp16 single ----------------
__global__ void __launch_bounds__(256) vT_k(const __half* __restrict__ qkvh,
                                            __half* __restrict__ vTh)
{
    __shared__ __half th[32][33];
    int b = blockIdx.z;
    int t0 = blockIdx.x * 32, c0 = blockIdx.y * 32;
    int tx = threadIdx.x & 31, ty = threadIdx.x >> 5;  // 32 x 8
#pragma unroll
    for (int i = 0; i < 4; i++) {
        int t = t0 + ty + i * 8;
        th[ty + i * 8][tx] = qkvh[((long)b * cT + t) * 384 + 256 + c0 + tx];
    }
    __syncthreads();
#pragma unroll
    for (int i = 0; i < 4; i++) {
        int c = c0 + ty + i * 8;
        int h = c >> 6, n = c & 63;
        vTh[((long)((b << 1) | h) * 64 + n) * cT + t0 + tx] = th[tx][ty + i * 8];
    }
}

// ---------------- p_w transpose to fp16 + fused pwn column sums ----------------
__global__ void __launch_bounds__(256) cvtT_k(const float* __restrict__ in,
                                              __half* __restrict__ oT,
                                              float* __restrict__ pwnsum)
{
    __shared__ float tile[32][33];
    __shared__ float colsum[32];
    int b = blockIdx.z;
    int o0 = blockIdx.x * 32, c0 = blockIdx.y * 32;
    int tx = threadIdx.x & 31, ty = threadIdx.x >> 5;  // 32 x 8
    const float* src = in + (long)b * cC * cC;
    if (threadIdx.x < 32) colsum[threadIdx.x] = 0.f;
    float s = 0.f;
#pragma unroll
    for (int i = 0; i < 4; i++) {
        int c = c0 + ty + i * 8;
        float v = src[(long)c * cC + o0 + tx];
        tile[ty + i * 8][tx] = v;
        s += v * v;
    }
    __syncthreads();
    atomicAdd(&colsum[tx], s);
    __half* dst = oT + (long)b * cC * cC;
#pragma unroll
    for (int i = 0; i < 4; i++) {
        int o = o0 + ty + i * 8;
        dst[(long)o * cC + c0 + tx] = __float2half_rn(tile[tx][ty + i * 8]);
    }
    __syncthreads();
    if (ty == 0) atomicAdd(&pwnsum[(long)b * cC + o0 + tx], colsum[tx]);
}

// ---------------- tiled depthwise conv (K=9): fp16 in, fp16 out ----------------
constexpr int CV_TR = 32;   // output t-rows per block
__global__ void __launch_bounds__(256) conv2_k(const __half* __restrict__ h,
                                               const float* __restrict__ d_w,
                                               const float* __restrict__ d_g,
                                               const float* __restrict__ d_b,
                                               const float* __restrict__ p_g,
                                               const float* __restrict__ dwn,
                                               __half* __restrict__ deph)
{
    __shared__ __half hs[CV_TR + 8][256];
    __shared__ float ws[9];
    int t0 = blockIdx.x * CV_TR, c0 = blockIdx.y * 256, b = blockIdx.z;
    int tid = threadIdx.x;
    if (tid < 9) ws[tid] = dwn[b * 9 + tid];
    __syncthreads();

#pragma unroll
    for (int i = tid; i < (CV_TR + 8) * 32; i += 256) {
        int r = i >> 5, q8 = i & 31;
        int t = t0 + r - 4;
        uint4 v = make_uint4(0u, 0u, 0u, 0u);
        if (t >= 0 && t < cT)
            v = *reinterpret_cast<const uint4*>(h + ((long)b * cT + t) * cC + c0 + q8 * 8);
        *reinterpret_cast<uint4*>(&hs[r][q8 * 8]) = v;
    }

    int c = c0 + tid;
    long bc = (long)b * cC + c;
    const float* wrow = d_w + bc * 9;
    float w[9];
#pragma unroll
    for (int k = 0; k < 9; k++) w[k] = wrow[k] * ws[k];
    float dg = d_g[bc], db = d_b[bc], pg = p_g[bc];
    __syncthreads();

#pragma unroll 4
    for (int tt = 0; tt < CV_TR; tt++) {
        float acc = 0.f;
#pragma unroll
        for (int k = 0; k < 9; k++) acc += __half2float(hs[tt + k][tid]) * w[k];
        float val = (acc * dg + db) * pg;
        deph[((long)b * cT + t0 + tt) * cC + c] = __float2half_rn(val);
    }
}

// ---------------- launch ----------------
extern "C" void kernel_launch(void* const* d_in, const int* in_sizes, int n_in,
                              void* d_out, int out_size)
{
    const float* x    = (const float*)d_in[0];
    const float* d_w  = (const float*)d_in[1];
    const float* d_g  = (const float*)d_in[2];
    const float* d_b  = (const float*)d_in[3];
    const float* p_w  = (const float*)d_in[4];
    const float* p_g  = (const float*)d_in[5];
    const float* p_b  = (const float*)d_in[6];
    const unsigned char* mask  = (const unsigned char*)d_in[7];
    const unsigned char* smask = (const unsigned char*)d_in[8];
    const float* Wq = (const float*)d_in[9];
    const float* bq = (const float*)d_in[10];
    const float* Wk = (const float*)d_in[11];
    const float* bk = (const float*)d_in[12];
    const float* Wv = (const float*)d_in[13];
    const float* bv = (const float*)d_in[14];
    const float* Wo = (const float*)d_in[15];
    const float* bo = (const float*)d_in[16];
    const float* g0 = (const float*)d_in[17];
    const float* b0 = (const float*)d_in[18];
    const float* w1_w = (const float*)d_in[19];
    const float* w1_b = (const float*)d_in[20];
    const float* w2_w = (const float*)d_in[21];
    const float* w2_b = (const float*)d_in[22];
    const float* g1 = (const float*)d_in[23];
    const float* b1 = (const float*)d_in[24];

    float* out  = (float*)d_out;
    float* attn = out + (long)cNT * cD;   // output tuple: (out[B,T,D], attn[B,H,T,T])

    float *apre, *a, *o2, *dwn, *pwn, *bqkv;
    __half *xh, *xl, *qkvh, *qkvl, *vTh, *atth, *ctxh, *ctxl;
    __half *ah, *hh, *deph, *pth, *pwT, *w1h, *w2h;
    __half *wqkvh, *wqkvl, *woh, *wol;
    cudaGetSymbolAddress((void**)&apre, g_apre);
    cudaGetSymbolAddress((void**)&a,    g_a);
    cudaGetSymbolAddress((void**)&o2,   g_o2);
    cudaGetSymbolAddress((void**)&dwn,  g_dwn);
    cudaGetSymbolAddress((void**)&pwn,  g_pwn);
    cudaGetSymbolAddress((void**)&bqkv, g_bqkv);
    cudaGetSymbolAddress((void**)&xh,   g_xh);
    cudaGetSymbolAddress((void**)&xl,   g_xl);
    cudaGetSymbolAddress((void**)&qkvh, g_qkvh);
    cudaGetSymbolAddress((void**)&qkvl, g_qkvl);
    cudaGetSymbolAddress((void**)&vTh,  g_vTh);
    cudaGetSymbolAddress((void**)&atth, g_atth);
    cudaGetSymbolAddress((void**)&ctxh, g_ctxh);
    cudaGetSymbolAddress((void**)&ctxl, g_ctxl);
    cudaGetSymbolAddress((void**)&ah,   g_ah);
    cudaGetSymbolAddress((void**)&hh,   g_hh);
    cudaGetSymbolAddress((void**)&deph, g_deph);
    cudaGetSymbolAddress((void**)&pth,  g_pth);
    cudaGetSymbolAddress((void**)&pwT,  g_pwT);
    cudaGetSymbolAddress((void**)&w1h,  g_w1);
    cudaGetSymbolAddress((void**)&w2h,  g_w2);
    cudaGetSymbolAddress((void**)&wqkvh, g_wqkv);
    cudaGetSymbolAddress((void**)&wqkvl, g_wqkvl);
    cudaGetSymbolAddress((void**)&woh,  g_wo);
    cudaGetSymbolAddress((void**)&wol,  g_wol);

    cudaFuncSetAttribute(mma_gemm1<2>,  cudaFuncAttributeMaxDynamicSharedMemorySize, MM_SMEM1);
    cudaFuncSetAttribute(mma_gemm1<9>,  cudaFuncAttributeMaxDynamicSharedMemorySize, MM_SMEM1);
    cudaFuncSetAttribute(mma_gemm1<10>, cudaFuncAttributeMaxDynamicSharedMemorySize, MM_SMEM1);
    cudaFuncSetAttribute(mma_gemm1s<8>, cudaFuncAttributeMaxDynamicSharedMemorySize, MM_SMEM1N);
    cudaFuncSetAttribute(mma_gemm3<2>, cudaFuncAttributeMaxDynamicSharedMemorySize, MM_SMEM3);
    cudaFuncSetAttribute(mma_gemm3<6>, cudaFuncAttributeMaxDynamicSharedMemorySize, MM_SMEM3);
    cudaFuncSetAttribute(mma_gemm3sc<5>, cudaFuncAttributeMaxDynamicSharedMemorySize, MM_SMEM3S);

    dim3 blk(256);

    // 0) prep (fused: weight cvt/splits, bqkv, pwn zero, dwn)
    wprep_k<<<dim3(256, 8), blk>>>(Wq, Wk, Wv, Wo, w1_w, w2_w, bq, bk, bv, d_w,
                                   wqkvh, wqkvl, woh, wol, w1h, w2h, bqkv, pwn, dwn);
    cvtT_k<<<dim3(32, 32, cB), blk>>>(p_w, pwT, pwn);
    cvt_split_h<<<(cNT * cD) / 1024, blk>>>(x, xh, xl, (long)cNT * cD);

    // 1) fused qkv projection (split out, 3-product): [16384,256] @ [384,256]^T
    mma_gemm3<6><<<dim3(3, cNT / 128, 1), blk, MM_SMEM3>>>(
        xh, xl, wqkvh, wqkvl, nullptr, qkvh, qkvl, cD, cD, cD, 384, 384, 1,
        0, 0, 0, 0, 0, 0, 0, 0, bqkv, nullptr);

    // 2) v -> vT (fp16 single, compact 64 rows per (b,h))
    vT_k<<<dim3(32, 4, cB), blk>>>(qkvh, vTh);

    // 3) scores = q k^T / 8  [3-product, nk=1 -> 1-stage smem, occ 2]
    mma_gemm3sc<5><<<dim3(8, 8, 32), blk, MM_SMEM3S>>>(
        qkvh, qkvl, qkvh + 128, qkvl + 128, attn, cDK, 384, 384, cT, 1024, 2,
        (long)cT * 384, 64, (long)cT * 384, 64, 2 * cTT, cTT);

    // 4) masked softmax (writes final attn + fp16 single)
    softmax_k<<<dim3(cT, cH, cB), blk>>>(attn, smask, atth);

    // 5) ctx = attn @ v  [1-product, BN=64] -> exact fp16 split of fp32 result
    mma_gemm1s<8><<<dim3(1, 8, 32), blk, MM_SMEM1N>>>(
        atth, vTh, ctxh, ctxl, cT, cT, cT, 128, 64, 2,
        2 * cTT, cTT, (long)128 * cT, (long)64 * cT, (long)cT * 128, 64);

    // 6) apre = ctx @ Wo^T + bo + x  [3-product]
    mma_gemm3<2><<<dim3(2, cNT / 128, 1), blk, MM_SMEM3>>>(
        ctxh, ctxl, woh, wol, apre, nullptr, nullptr, 128, 128, 128, cD, 256, 1,
        0, 0, 0, 0, 0, 0, 0, 0, bo, x);

    // 7) a = LN(apre), masked; emit fp16 single
    ln_k<<<cNT, blk>>>(apre, g0, b0, mask, a, ah);

    // 8) h = mish(a @ w1^T + w1_b) -> fp16 single  [1-product, 3-stage, occ 2]
    mma_gemm1<9><<<dim3(cC / 128, cNT / 128, 1), blk, MM_SMEM1>>>(
        ah, w1h, nullptr, hh, cD, cD, cD, cC, 1024, 1,
        0, 0, 0, 0, 0, 0, 0, 0, w1_b, nullptr);

    // 9) tiled depthwise conv (fp16 in/out)
    conv2_k<<<dim3(cT / CV_TR, cC / 256, cB), blk>>>(hh, d_w, d_g, d_b, p_g, dwn, deph);

    // 10) pt = (dep @ pwT) * invnorm(pwnsum[o]) + p_b -> fp16 single  [1-prod, batched]
    mma_gemm1<10><<<dim3(cC / 128, cT / 128, cB), blk, MM_SMEM1>>>(
        deph, pwT, nullptr, pth, cC, cC, cC, cC, 1024, 1,
        (long)cT * cC, 0, (long)cC * cC, 0, (long)cT * cC, 0, cC, cC, p_b, pwn);

    // 11) o2 = pt @ w2^T + w2_b + a  [1-product]
    mma_gemm1<2><<<dim3(cD / 128, cNT / 128, 1), blk, MM_SMEM1>>>(
        pth, w2h, o2, nullptr, cC, cC, cC, cD, 256, 1,
        0, 0, 0, 0, 0, 0, 0, 0, w2_b, a);

    // 12) out = LN(o2), masked
    ln_k<<<cNT, blk>>>(o2, g1, b1, mask, out, nullptr);
}

// round 16
// speedup vs baseline: 1.0621x; 1.0621x over previous
#include <cuda_runtime.h>
#include <cuda_fp16.h>
#include <cstdint>
#include <math.h>

// ---------------- problem constants ----------------
constexpr int cB = 16, cT = 1024, cD = 256, cH = 2, cDK = 64, cC = 1024;
constexpr int cNT = cB * cT;            // 16384 tokens
constexpr long cTT = (long)cT * cT;     // 1M
constexpr float LN_EPS = 1e-5f;

// ---------------- device scratch (no allocs allowed) ----------------
__device__ float g_apre[cNT * cD];
__device__ float g_a   [cNT * cD];
__device__ float g_o2 [cNT * cD];
__device__ float g_dwn[cB * 9];
__device__ float g_pwn[cB * cC];        // sum of squares (atomic); inv-norm applied inline in pt epilogue
__device__ float g_bqkv[384];
// fp16 buffers
__device__ __half g_xh  [cNT * cD];
__device__ __half g_xl  [cNT * cD];
__device__ __half g_qkvh[cNT * 384];
__device__ __half g_qkvl[cNT * 384];
__device__ __half g_vTh [(long)cB * cH * 64 * cT];    // compact 64 rows per (b,h)
__device__ __half g_atth[(long)cB * cH * cTT];
__device__ __half g_ctxh[cNT * 128];
__device__ __half g_ctxl[cNT * 128];
__device__ __half g_ah  [cNT * cD];
__device__ __half g_hh  [cNT * cC];
__device__ __half g_deph[cNT * cC];
__device__ __half g_pth [cNT * cC];
__device__ __half g_pwT [(long)cB * cC * cC];
__device__ __half g_w1  [cC * cD];
__device__ __half g_w2  [cD * cC];
__device__ __half g_wqkv [384 * cD];
__device__ __half g_wqkvl[384 * cD];
__device__ __half g_wo  [cD * 128];
__device__ __half g_wol [cD * 128];

// ---------------- helpers ----------------
__device__ __forceinline__ uint32_t smem_u32(const void* p) {
    uint32_t a;
    asm("{ .reg .u64 t; cvta.to.shared.u64 t, %1; cvt.u32.u64 %0, t; }" : "=r"(a) : "l"(p));
    return a;
}
#define SW128(off) ((off) ^ (((off) >> 3) & 0x70))

__device__ __forceinline__ void split_h(float v, __half& h, __half& l) {
    h = __float2half_rn(v);
    l = __float2half_rn(v - __half2float(h));
}

__device__ __forceinline__ void ldsm4(uint32_t* r, uint32_t addr) {
    asm volatile("ldmatrix.sync.aligned.m8n8.x4.shared.b16 {%0,%1,%2,%3}, [%4];"
        : "=r"(r[0]), "=r"(r[1]), "=r"(r[2]), "=r"(r[3]) : "r"(addr));
}
__device__ __forceinline__ void mma16816(float* d, const uint32_t* a, const uint32_t* b) {
    asm volatile("mma.sync.aligned.m16n8k16.row.col.f32.f16.f16.f32 "
        "{%0,%1,%2,%3}, {%4,%5,%6,%7}, {%8,%9}, {%0,%1,%2,%3};"
        : "+f"(d[0]), "+f"(d[1]), "+f"(d[2]), "+f"(d[3])
        : "r"(a[0]), "r"(a[1]), "r"(a[2]), "r"(a[3]), "r"(b[0]), "r"(b[1]));
}
__device__ __forceinline__ void cp16(uint32_t saddr, const void* gptr) {
    asm volatile("cp.async.cg.shared.global [%0], [%1], 16;"
        :: "r"(saddr), "l"(__cvta_generic_to_global(gptr)));
}
__device__ __forceinline__ void cp_commit() {
    asm volatile("cp.async.commit_group;");
}
template<int N>
__device__ __forceinline__ void cp_wait() {
    asm volatile("cp.async.wait_group %0;" :: "n"(N));
}

__device__ __forceinline__ float warpReduceSum(float v) {
#pragma unroll
    for (int o = 16; o > 0; o >>= 1) v += __shfl_xor_sync(0xffffffffu, v, o);
    return v;
}
__device__ __forceinline__ float warpReduceMax(float v) {
#pragma unroll
    for (int o = 16; o > 0; o >>= 1) v = fmaxf(v, __shfl_xor_sync(0xffffffffu, v, o));
    return v;
}

// ---------------- mma.sync fp16 GEMM body (R14 pipeline structure) ----------------
// D[M,N] = A[M,K] @ B[N,K]^T.  Tile 128 x BN (BN=128 or 64), BK=64.
// NPROD=1: A,B single fp16 (3-stage).  NPROD=3: A and B split (2-stage).
// EPI: 2 = +bias[n]+aux residual -> f32 | 5 = acc*0.125 -> f32
//      6 = +bias -> fp16 split | 8 = raw -> fp16 split
//      9 = mish(acc+bias) -> fp16 single
//      10 = acc * invnorm(aux[n]) + bias[n] -> fp16 single (aux = raw sum of squares)
constexpr int MM_SMEM1  = 3 * 32768 + 1024;            // 1-prod, BN=128, 3 stages
constexpr int MM_SMEM1N = 3 * 24576 + 1024;            // 1-prod, BN=64,  3 stages
constexpr int MM_SMEM3  = 2 * 65536 + 1024;            // 3-prod, BN=128, 2 stages
constexpr int MM_SMEM3S = 1 * 65536 + 1024;            // 3-prod, BN=128, nk=1 (scores)

template<int EPI, int NPROD, int BN>
__device__ __forceinline__ void mma_body(
    const __half* __restrict__ Ah, const __half* __restrict__ Al,
    const __half* __restrict__ Bh, const __half* __restrict__ Bl,
    float* __restrict__ C, __half* __restrict__ Ch, __half* __restrict__ Cl,
    int Kd, int lda, int ldb, int ldc, int nLim, int zdiv,
    long aQ, long aR, long bQ, long bR, long cQ, long cR,
    long biasZ, long auxZ,
    const float* __restrict__ bias, const float* __restrict__ aux)
{
    constexpr int ASZ  = 16384;            // 128 rows x 64 cols fp16
    constexpr int BSZ  = BN * 128;
    constexpr int NAt  = (NPROD >= 2) ? 2 : 1;
    constexpr int NBt  = (NPROD == 3) ? 2 : 1;
    constexpr int BOFF = NAt * ASZ;
    constexpr int STAGE = NAt * ASZ + NBt * BSZ;
    constexpr int NSTG  = (NPROD == 1) ? 3 : 2;
    constexpr int NBT   = BN / 32;         // 16-col subtiles per warp-half (4 or 2)
    extern __shared__ char sm_raw[];
    uint32_t sb0 = smem_u32(sm_raw);
    uint32_t sb  = (sb0 + 1023u) & ~1023u;

    int z = blockIdx.z;
    int zq = z / zdiv, zr = z - zq * zdiv;
    long aoff = (long)zq * aQ + (long)zr * aR;
    long boff = (long)zq * bQ + (long)zr * bR;
    long coff = (long)zq * cQ + (long)zr * cR;
    Ah += aoff;
    if (NPROD >= 2) Al += aoff;
    Bh += boff;
    if (NPROD == 3) Bl += boff;
    if (C)  C  += coff;
    if (Ch) Ch += coff;
    if (Cl) Cl += coff;
    const float* biasp = bias ? bias + (long)zq * biasZ : nullptr;
    const float* auxp  = aux  ? aux  + (long)zq * auxZ  : nullptr;

    int m0 = blockIdx.y * 128, n0 = blockIdx.x * BN;
    int tid = threadIdx.x, wid = tid >> 5, lane = tid & 31;
    int wm = wid & 3, wn = wid >> 2;

    int lrow = tid >> 3, lcq = tid & 7;

    auto issue_stage = [&](int k0, uint32_t sbase) {
#pragma unroll
        for (int ti = 0; ti < 4; ti++) {
            int row = lrow + ti * 32;
            uint32_t soff = SW128((uint32_t)(row * 128 + lcq * 16));
            long ga = (long)(m0 + row) * lda + k0 + lcq * 8;
            cp16(sbase + soff, Ah + ga);
            if (NPROD >= 2) cp16(sbase + ASZ + soff, Al + ga);
        }
#pragma unroll
        for (int ti = 0; ti < BN / 32; ti++) {
            int row = lrow + ti * 32;
            uint32_t soff = SW128((uint32_t)(row * 128 + lcq * 16));
            long gb = (long)(n0 + row) * ldb + k0 + lcq * 8;
            cp16(sbase + BOFF + soff, Bh + gb);
            if (NPROD == 3) cp16(sbase + BOFF + BSZ + soff, Bl + gb);
        }
        cp_commit();
    };

    float acc[2][BN / 16][4];
#pragma unroll
    for (int i = 0; i < 2; i++)
#pragma unroll
        for (int j = 0; j < BN / 16; j++)
#pragma unroll
            for (int l = 0; l < 4; l++) acc[i][j][l] = 0.f;

    int nk = Kd >> 6;
#pragma unroll
    for (int s = 0; s < NSTG - 1; s++)
        if (s < nk) issue_stage(s << 6, sb + (uint32_t)s * STAGE);

    for (int i = 0; i < nk; i++) {
        uint32_t cur = sb + (uint32_t)(i % NSTG) * STAGE;
        int j = i + NSTG - 1;
        if (j < nk) issue_stage(j << 6, sb + (uint32_t)(j % NSTG) * STAGE);
        int rem = nk - 1 - i;
        if (NSTG == 3) {
            if (rem >= 2) cp_wait<2>();
            else if (rem == 1) cp_wait<1>();
            else cp_wait<0>();
        } else {
            if (rem >= 1) cp_wait<1>();
            else cp_wait<0>();
        }
        __syncthreads();

        uint32_t uAh = cur, uAl = cur + ASZ, uBh = cur + BOFF, uBl = cur + BOFF + BSZ;
#pragma unroll
        for (int ks = 0; ks < 4; ks++) {
            uint32_t afh[2][4], afl[2][4], bfh[NBT][4], bfl[NBT][4];
#pragma unroll
            for (int mt = 0; mt < 2; mt++) {
                int r = wm * 32 + mt * 16 + (lane & 15);
                int kc = ks * 2 + (lane >> 4);
                uint32_t off = SW128((uint32_t)(r * 128 + kc * 16));
                ldsm4(afh[mt], uAh + off);
                if (NPROD >= 2) ldsm4(afl[mt], uAl + off);
            }
#pragma unroll
            for (int bt = 0; bt < NBT; bt++) {
                int r = wn * (BN / 2) + bt * 16 + (lane & 7) + ((lane >> 4) << 3);
                int kc = ks * 2 + ((lane >> 3) & 1);
                uint32_t off = SW128((uint32_t)(r * 128 + kc * 16));
                ldsm4(bfh[bt], uBh + off);
                if (NPROD == 3) ldsm4(bfl[bt], uBl + off);
            }
#pragma unroll
            for (int p = 0; p < NPROD; p++)
#pragma unroll
                for (int mt = 0; mt < 2; mt++)
#pragma unroll
                    for (int bt = 0; bt < NBT; bt++)
#pragma unroll
                        for (int hh = 0; hh < 2; hh++) {
                            const uint32_t* af  = (p == 1) ? afl[mt] : afh[mt];
                            const uint32_t* bfp = (p == 2) ? &bfl[bt][hh * 2] : &bfh[bt][hh * 2];
                            mma16816(acc[mt][bt * 2 + hh], af, bfp);
                        }
        }
        __syncthreads();
    }

    // epilogue
#pragma unroll
    for (int mt = 0; mt < 2; mt++)
#pragma unroll
        for (int bt = 0; bt < NBT; bt++)
#pragma unroll
            for (int hh = 0; hh < 2; hh++) {
                float* d = acc[mt][bt * 2 + hh];
                int col = n0 + wn * (BN / 2) + bt * 16 + hh * 8 + (lane & 3) * 2;
                int r0  = m0 + wm * 32 + mt * 16 + (lane >> 2);
                if (col >= nLim) continue;
#pragma unroll
                for (int half = 0; half < 2; half++) {
                    int row = r0 + half * 8;
                    float t0 = d[half * 2 + 0], t1 = d[half * 2 + 1];
                    if (EPI == 2) {
                        t0 += biasp[col]     + auxp[(long)row * ldc + col];
                        t1 += biasp[col + 1] + auxp[(long)row * ldc + col + 1];
                        float2 v = {t0, t1};
                        *reinterpret_cast<float2*>(C + (long)row * ldc + col) = v;
                    } else if (EPI == 5) {
                        float2 v = {t0 * 0.125f, t1 * 0.125f};
                        *reinterpret_cast<float2*>(C + (long)row * ldc + col) = v;
                    } else if (EPI == 9) {
                        t0 += biasp[col];
                        t1 += biasp[col + 1];
                        float sp0 = (t0 > 20.f) ? t0 : log1pf(expf(t0));
                        float sp1 = (t1 > 20.f) ? t1 : log1pf(expf(t1));
                        t0 = t0 * tanhf(sp0);
                        t1 = t1 * tanhf(sp1);
                        __half2 hv = {__float2half_rn(t0), __float2half_rn(t1)};
                        *reinterpret_cast<__half2*>(Ch + (long)row * ldc + col) = hv;
                    } else if (EPI == 10) {
                        float inv0 = 1.f / fmaxf(sqrtf(auxp[col]),     1e-12f);
                        float inv1 = 1.f / fmaxf(sqrtf(auxp[col + 1]), 1e-12f);
                        t0 = t0 * inv0 + biasp[col];
                        t1 = t1 * inv1 + biasp[col + 1];
                        __half2 hv = {__float2half_rn(t0), __float2half_rn(t1)};
                        *reinterpret_cast<__half2*>(Ch + (long)row * ldc + col) = hv;
                    } else { // 6, 8: fp16 split outputs
                        if (EPI == 6) {
                            t0 += biasp[col];
                            t1 += biasp[col + 1];
                        }
                        __half h0, l0, h1, l1;
                        split_h(t0, h0, l0);
                        split_h(t1, h1, l1);
                        __half2 hv = {h0, h1}, lv = {l0, l1};
                        *reinterpret_cast<__half2*>(Ch + (long)row * ldc + col) = hv;
                        *reinterpret_cast<__half2*>(Cl + (long)row * ldc + col) = lv;
                    }
                }
            }
}

template<int EPI>
__global__ void __launch_bounds__(256, 2) mma_gemm1(
    const __half* __restrict__ Ah, const __half* __restrict__ Bh,
    float* __restrict__ C, __half* __restrict__ Ch,
    int Kd, int lda, int ldb, int ldc, int nLim, int zdiv,
    long aQ, long aR, long bQ, long bR, long cQ, long cR,
    long biasZ, long auxZ,
    const float* __restrict__ bias, const float* __restrict__ aux)
{
    mma_body<EPI, 1, 128>(Ah, nullptr, Bh, nullptr, C, Ch, nullptr, Kd, lda, ldb, ldc, nLim, zdiv,
                          aQ, aR, bQ, bR, cQ, cR, biasZ, auxZ, bias, aux);
}

// 1-product, BN=64, split fp16 output (for ctx)
template<int EPI>
__global__ void __launch_bounds__(256, 2) mma_gemm1s(
    const __half* __restrict__ Ah, const __half* __restrict__ Bh,
    __half* __restrict__ Ch, __half* __restrict__ Cl,
    int Kd, int lda, int ldb, int ldc, int nLim, int zdiv,
    long aQ, long aR, long bQ, long bR, long cQ, long cR)
{
    mma_body<EPI, 1, 64>(Ah, nullptr, Bh, nullptr, nullptr, Ch, Cl, Kd, lda, ldb, ldc, nLim, zdiv,
                         aQ, aR, bQ, bR, cQ, cR, 0, 0, nullptr, nullptr);
}

template<int EPI>
__global__ void __launch_bounds__(256) mma_gemm3(
    const __half* __restrict__ Ah, const __half* __restrict__ Al,
    const __half* __restrict__ Bh, const __half* __restrict__ Bl,
    float* __restrict__ C, __half* __restrict__ Ch, __half* __restrict__ Cl,
    int Kd, int lda, int ldb, int ldc, int nLim, int zdiv,
    long aQ, long aR, long bQ, long bR, long cQ, long cR,
    long biasZ, long auxZ,
    const float* __restrict__ bias, const float* __restrict__ aux)
{
    mma_body<EPI, 3, 128>(Ah, Al, Bh, Bl, C, Ch, Cl, Kd, lda, ldb, ldc, nLim, zdiv,
                          aQ, aR, bQ, bR, cQ, cR, biasZ, auxZ, bias, aux);
}

// scores-specific: reg-capped for 2 CTAs/SM, launched with 1-stage smem (nk=1)
template<int EPI>
__global__ void __launch_bounds__(256, 2) mma_gemm3sc(
    const __half* __restrict__ Ah, const __half* __restrict__ Al,
    const __half* __restrict__ Bh, const __half* __restrict__ Bl,
    float* __restrict__ C,
    int Kd, int lda, int ldb, int ldc, int nLim, int zdiv,
    long aQ, long aR, long bQ, long bR, long cQ, long cR)
{
    mma_body<EPI, 3, 128>(Ah, Al, Bh, Bl, C, nullptr, nullptr, Kd, lda, ldb, ldc, nLim, zdiv,
                          aQ, aR, bQ, bR, cQ, cR, 0, 0, nullptr, nullptr);
}

// ---------------- softmax (in place; emits fp16 single; vectorized) ----------------
__global__ void __launch_bounds__(256) softmax_k(float* __restrict__ attn,
                                                 const unsigned char* __restrict__ smask,
                                                 __half* __restrict__ ath)
{
    int i = blockIdx.x, h = blockIdx.y, b = blockIdx.z;
    long rbase = (((long)(b * cH + h)) * cT + i) * cT;
    float* row = attn + rbase;
    const unsigned char* mrow = smask + ((long)b * cT + i) * cT;
    int tid = threadIdx.x, lane = tid & 31, wid = tid >> 5;
    __shared__ float red[8];
    __shared__ float bc;

    float4 v4 = *reinterpret_cast<const float4*>(row + tid * 4);
    uchar4 m4 = *reinterpret_cast<const uchar4*>(mrow + tid * 4);
    float v[4] = {v4.x, v4.y, v4.z, v4.w};
    if (m4.x) v[0] = -1e9f;
    if (m4.y) v[1] = -1e9f;
    if (m4.z) v[2] = -1e9f;
    if (m4.w) v[3] = -1e9f;
    float mx = fmaxf(fmaxf(v[0], v[1]), fmaxf(v[2], v[3]));
    mx = warpReduceMax(mx);
    if (lane == 0) red[wid] = mx;
    __syncthreads();
    if (wid == 0) {
        float r = (lane < 8) ? red[lane] : -3.4e38f;
        r = warpReduceMax(r);
        if (lane == 0) bc = r;
    }
    __syncthreads();
    mx = bc;
    float sum = 0.f;
#pragma unroll
    for (int r = 0; r < 4; r++) { v[r] = expf(v[r] - mx); sum += v[r]; }
    __syncthreads();
    sum = warpReduceSum(sum);
    if (lane == 0) red[wid] = sum;
    __syncthreads();
    if (wid == 0) {
        float r = (lane < 8) ? red[lane] : 0.f;
        r = warpReduceSum(r);
        if (lane == 0) bc = r;
    }
    __syncthreads();
    float inv = 1.f / bc;
    float4 o = {v[0] * inv, v[1] * inv, v[2] * inv, v[3] * inv};
    *reinterpret_cast<float4*>(row + tid * 4) = o;
    __half2 h01 = {__float2half_rn(o.x), __float2half_rn(o.y)};
    __half2 h23 = {__float2half_rn(o.z), __float2half_rn(o.w)};
    *reinterpret_cast<__half2*>(ath + rbase + tid * 4)     = h01;
    *reinterpret_cast<__half2*>(ath + rbase + tid * 4 + 2) = h23;
}

// ---------------- LayerNorm: warp-per-token (8 tokens/CTA), no block sync ----------------
__global__ void __launch_bounds__(256) ln_k(const float* __restrict__ in,
                                            const float* __restrict__ g,
                                            const float* __restrict__ bta,
                                            const unsigned char* __restrict__ mask,
                                            float* __restrict__ out,
                                            __half* __restrict__ oh)
{
    int wid = threadIdx.x >> 5, lane = threadIdx.x & 31;
    long n = (long)blockIdx.x * 8 + wid;
    const float* src = in + n * cD + lane * 8;
    float4 a = *reinterpret_cast<const float4*>(src);
    float4 b = *reinterpret_cast<const float4*>(src + 4);
    float s  = (a.x + a.y) + (a.z + a.w) + (b.x + b.y) + (b.z + b.w);
    float s2 = (a.x * a.x + a.y * a.y) + (a.z * a.z + a.w * a.w)
             + (b.x * b.x + b.y * b.y) + (b.z * b.z + b.w * b.w);
    s  = warpReduceSum(s);
    s2 = warpReduceSum(s2);
    float mean = s * (1.f / cD);
    float var  = s2 * (1.f / cD) - mean * mean;
    float rstd = rsqrtf(var + LN_EPS);
    bool msk = mask[n];
    int c0 = lane * 8;
    const float4 g0 = *reinterpret_cast<const float4*>(g + c0);
    const float4 g1 = *reinterpret_cast<const float4*>(g + c0 + 4);
    const float4 t0 = *reinterpret_cast<const float4*>(bta + c0);
    const float4 t1 = *reinterpret_cast<const float4*>(bta + c0 + 4);
    float y[8];
    y[0] = (a.x - mean) * rstd * g0.x + t0.x;
    y[1] = (a.y - mean) * rstd * g0.y + t0.y;
    y[2] = (a.z - mean) * rstd * g0.z + t0.z;
    y[3] = (a.w - mean) * rstd * g0.w + t0.w;
    y[4] = (b.x - mean) * rstd * g1.x + t1.x;
    y[5] = (b.y - mean) * rstd * g1.y + t1.y;
    y[6] = (b.z - mean) * rstd * g1.z + t1.z;
    y[7] = (b.w - mean) * rstd * g1.w + t1.w;
    if (msk) {
#pragma unroll
        for (int j = 0; j < 8; j++) y[j] = 0.f;
    }
    float* dst = out + n * cD + c0;
    *reinterpret_cast<float4*>(dst)     = make_float4(y[0], y[1], y[2], y[3]);
    *reinterpret_cast<float4*>(dst + 4) = make_float4(y[4], y[5], y[6], y[7]);
    if (oh) {
        __half* hd = oh + n * cD + c0;
#pragma unroll
        for (int j = 0; j < 8; j += 2) {
            __half2 hv = {__float2half_rn(y[j]), __float2half_rn(y[j + 1])};
            *reinterpret_cast<__half2*>(hd + j) = hv;
        }
    }
}

// ---------------- fused small weight prep (one launch) ----------------
__device__ __forceinline__ void split4_at(const float* in, __half* oh, __half* ol, long i) {
    float4 v = *reinterpret_cast<const float4*>(in + i);
    __half h0, h1, h2, h3, l0, l1, l2, l3;
    split_h(v.x, h0, l0); split_h(v.y, h1, l1);
    split_h(v.z, h2, l2); split_h(v.w, h3, l3);
    __half2 ha = {h0, h1}, hb = {h2, h3}, la = {l0, l1}, lb = {l2, l3};
    *reinterpret_cast<__half2*>(oh + i)     = ha;
    *reinterpret_cast<__half2*>(oh + i + 2) = hb;
    *reinterpret_cast<__half2*>(ol + i)     = la;
    *reinterpret_cast<__half2*>(ol + i + 2) = lb;
}
__device__ __forceinline__ void cvt4_at(const float* in, __half* o, long i) {
    float4 v = *reinterpret_cast<const float4*>(in + i);
    __half2 a = {__float2half_rn(v.x), __float2half_rn(v.y)};
    __half2 b = {__float2half_rn(v.z), __float2half_rn(v.w)};
    *reinterpret_cast<__half2*>(o + i)     = a;
    *reinterpret_cast<__half2*>(o + i + 2) = b;
}

__global__ void __launch_bounds__(256) wprep_k(
    const float* __restrict__ Wq, const float* __restrict__ Wk,
    const float* __restrict__ Wv, const float* __restrict__ Wo,
    const float* __restrict__ w1, const float* __restrict__ w2,
    const float* __restrict__ bq, const float* __restrict__ bk,
    const float* __restrict__ bv,
    const float* __restrict__ d_w,
    __half* __restrict__ wqkvh, __half* __restrict__ wqkvl,
    __half* __restrict__ woh, __half* __restrict__ wol,
    __half* __restrict__ w1h, __half* __restrict__ w2h,
    float* __restrict__ bqkv, float* __restrict__ pwnsum,
    float* __restrict__ dwn)
{
    int task = blockIdx.y;
    long i = ((long)blockIdx.x * 256 + threadIdx.x) * 4;
    constexpr long SZp = (long)128 * cD;  // 32768
    constexpr long SZw = (long)cC * cD;   // 262144
    if (task == 0) { if (i < SZp) split4_at(Wq, wqkvh, wqkvl, i); }
    else if (task == 1) { if (i < SZp) split4_at(Wk, wqkvh + SZp, wqkvl + SZp, i); }
    else if (task == 2) { if (i < SZp) split4_at(Wv, wqkvh + 2 * SZp, wqkvl + 2 * SZp, i); }
    else if (task == 3) { if (i < SZp) split4_at(Wo, woh, wol, i); }
    else if (task == 4) { if (i < SZw) cvt4_at(w1, w1h, i); }
    else if (task == 5) { if (i < SZw) cvt4_at(w2, w2h, i); }
    else if (task == 6) {
        long t = (long)blockIdx.x * 256 + threadIdx.x;
        if (t < 128) bqkv[t] = bq[t];
        else if (t < 256) bqkv[t] = bk[t - 128];
        else if (t < 384) bqkv[t] = bv[t - 256];
        if (t < (long)cB * cC) pwnsum[t] = 0.f;
    } else { // 7: per-b depthwise weight inverse norms
        int b = blockIdx.x;
        if (b >= cB) return;
        int tid = threadIdx.x, lane = tid & 31;
        __shared__ float red9[9];
        if (tid < 9) red9[tid] = 0.f;
        __syncthreads();
        float s[9];
#pragma unroll
        for (int k = 0; k < 9; k++) s[k] = 0.f;
        for (int c = tid; c < cC; c += 256) {
            const float* wr = d_w + ((long)b * cC + c) * 9;
#pragma unroll
            for (int k = 0; k < 9; k++) { float w = wr[k]; s[k] += w * w; }
        }
#pragma unroll
        for (int k = 0; k < 9; k++) {
            float r = warpReduceSum(s[k]);
            if (lane == 0) atomicAdd(&red9[k], r);
        }
        __syncthreads();
        if (tid < 9)
            dwn[b * 9 + tid] = 1.f / fmaxf(sqrtf(red9[tid]), 1e-12f);
    }
}

// ---------------- fp32 -> fp16 hi/lo split (x) ----------------
__global__ void __launch_bounds__(256) cvt_split_h(const float* __restrict__ in,
                                                   __half* __restrict__ oh,
                                                   __half* __restrict__ ol, long n)
{
    long i = ((long)blockIdx.x * 256 + threadIdx.x) * 4;
    if (i >= n) return;
    split4_at(in, oh, ol, i);
}

// ---------------- qkv cols 256..383 (v) -> vT [(b,h)][n(64)][t] fp16 single ----------------
__global__ void __launch_bounds__(256) vT_k(const __half* __restrict__ qkvh,
                                            __half* __restrict__ vTh)
{
    __shared__ __half th[32][33];
    int b = blockIdx.z;
    int t0 = blockIdx.x * 32, c0 = blockIdx.y * 32;
    int tx = threadIdx.x & 31, ty = threadIdx.x >> 5;  // 32 x 8
#pragma unroll
    for (int i = 0; i < 4; i++) {
        int t = t0 + ty + i * 8;
        th[ty + i * 8][tx] = qkvh[((long)b * cT + t) * 384 + 256 + c0 + tx];
    }
    __syncthreads();
#pragma unroll
    for (int i = 0; i < 4; i++) {
        int c = c0 + ty + i * 8;
        int h = c >> 6, n = c & 63;
        vTh[((long)((b << 1) | h) * 64 + n) * cT + t0 + tx] = th[tx][ty + i * 8];
    }
}

// ---------------- p_w transpose to fp16 + fused pwn column sums ----------------
__global__ void __launch_bounds__(256) cvtT_k(const float* __restrict__ in,
                                              __half* __restrict__ oT,
                                              float* __restrict__ pwnsum)
{
    __shared__ float tile[32][33];
    __shared__ float colsum[32];
    int b = blockIdx.z;
    int o0 = blockIdx.x * 32, c0 = blockIdx.y * 32;
    int tx = threadIdx.x & 31, ty = threadIdx.x >> 5;  // 32 x 8
    const float* src = in + (long)b * cC * cC;
    if (threadIdx.x < 32) colsum[threadIdx.x] = 0.f;
    float s = 0.f;
#pragma unroll
    for (int i = 0; i < 4; i++) {
        int c = c0 + ty + i * 8;
        float v = src[(long)c * cC + o0 + tx];
        tile[ty + i * 8][tx] = v;
        s += v * v;
    }
    __syncthreads();
    atomicAdd(&colsum[tx], s);
    __half* dst = oT + (long)b * cC * cC;
#pragma unroll
    for (int i = 0; i < 4; i++) {
        int o = o0 + ty + i * 8;
        dst[(long)o * cC + c0 + tx] = __float2half_rn(tile[tx][ty + i * 8]);
    }
    __syncthreads();
    if (ty == 0) atomicAdd(&pwnsum[(long)b * cC + o0 + tx], colsum[tx]);
}

// ---------------- tiled depthwise conv (K=9): fp16 in, fp16 out ----------------
constexpr int CV_TR = 32;   // output t-rows per block
__global__ void __launch_bounds__(256) conv2_k(const __half* __restrict__ h,
                                               const float* __restrict__ d_w,
                                               const float* __restrict__ d_g,
                                               const float* __restrict__ d_b,
                                               const float* __restrict__ p_g,
                                               const float* __restrict__ dwn,
                                               __half* __restrict__ deph)
{
    __shared__ __half hs[CV_TR + 8][256];
    __shared__ float ws[9];
    int t0 = blockIdx.x * CV_TR, c0 = blockIdx.y * 256, b = blockIdx.z;
    int tid = threadIdx.x;
    if (tid < 9) ws[tid] = dwn[b * 9 + tid];
    __syncthreads();

#pragma unroll
    for (int i = tid; i < (CV_TR + 8) * 32; i += 256) {
        int r = i >> 5, q8 = i & 31;
        int t = t0 + r - 4;
        uint4 v = make_uint4(0u, 0u, 0u, 0u);
        if (t >= 0 && t < cT)
            v = *reinterpret_cast<const uint4*>(h + ((long)b * cT + t) * cC + c0 + q8 * 8);
        *reinterpret_cast<uint4*>(&hs[r][q8 * 8]) = v;
    }

    int c = c0 + tid;
    long bc = (long)b * cC + c;
    const float* wrow = d_w + bc * 9;
    float w[9];
#pragma unroll
    for (int k = 0; k < 9; k++) w[k] = wrow[k] * ws[k];
    float dg = d_g[bc], db = d_b[bc], pg = p_g[bc];
    __syncthreads();

#pragma unroll 4
    for (int tt = 0; tt < CV_TR; tt++) {
        float acc = 0.f;
#pragma unroll
        for (int k = 0; k < 9; k++) acc += __half2float(hs[tt + k][tid]) * w[k];
        float val = (acc * dg + db) * pg;
        deph[((long)b * cT + t0 + tt) * cC + c] = __float2half_rn(val);
    }
}

// ---------------- launch ----------------
extern "C" void kernel_launch(void* const* d_in, const int* in_sizes, int n_in,
                              void* d_out, int out_size)
{
    const float* x    = (const float*)d_in[0];
    const float* d_w  = (const float*)d_in[1];
    const float* d_g  = (const float*)d_in[2];
    const float* d_b  = (const float*)d_in[3];
    const float* p_w  = (const float*)d_in[4];
    const float* p_g  = (const float*)d_in[5];
    const float* p_b  = (const float*)d_in[6];
    const unsigned char* mask  = (const unsigned char*)d_in[7];
    const unsigned char* smask = (const unsigned char*)d_in[8];
    const float* Wq = (const float*)d_in[9];
    const float* bq = (const float*)d_in[10];
    const float* Wk = (const float*)d_in[11];
    const float* bk = (const float*)d_in[12];
    const float* Wv = (const float*)d_in[13];
    const float* bv = (const float*)d_in[14];
    const float* Wo = (const float*)d_in[15];
    const float* bo = (const float*)d_in[16];
    const float* g0 = (const float*)d_in[17];
    const float* b0 = (const float*)d_in[18];
    const float* w1_w = (const float*)d_in[19];
    const float* w1_b = (const float*)d_in[20];
    const float* w2_w = (const float*)d_in[21];
    const float* w2_b = (const float*)d_in[22];
    const float* g1 = (const float*)d_in[23];
    const float* b1 = (const float*)d_in[24];

    float* out  = (float*)d_out;
    float* attn = out + (long)cNT * cD;   // output tuple: (out[B,T,D], attn[B,H,T,T])

    float *apre, *a, *o2, *dwn, *pwn, *bqkv;
    __half *xh, *xl, *qkvh, *qkvl, *vTh, *atth, *ctxh, *ctxl;
    __half *ah, *hh, *deph, *pth, *pwT, *w1h, *w2h;
    __half *wqkvh, *wqkvl, *woh, *wol;
    cudaGetSymbolAddress((void**)&apre, g_apre);
    cudaGetSymbolAddress((void**)&a,    g_a);
    cudaGetSymbolAddress((void**)&o2,   g_o2);
    cudaGetSymbolAddress((void**)&dwn,  g_dwn);
    cudaGetSymbolAddress((void**)&pwn,  g_pwn);
    cudaGetSymbolAddress((void**)&bqkv, g_bqkv);
    cudaGetSymbolAddress((void**)&xh,   g_xh);
    cudaGetSymbolAddress((void**)&xl,   g_xl);
    cudaGetSymbolAddress((void**)&qkvh, g_qkvh);
    cudaGetSymbolAddress((void**)&qkvl, g_qkvl);
    cudaGetSymbolAddress((void**)&vTh,  g_vTh);
    cudaGetSymbolAddress((void**)&atth, g_atth);
    cudaGetSymbolAddress((void**)&ctxh, g_ctxh);
    cudaGetSymbolAddress((void**)&ctxl, g_ctxl);
    cudaGetSymbolAddress((void**)&ah,   g_ah);
    cudaGetSymbolAddress((void**)&hh,   g_hh);
    cudaGetSymbolAddress((void**)&deph, g_deph);
    cudaGetSymbolAddress((void**)&pth,  g_pth);
    cudaGetSymbolAddress((void**)&pwT,  g_pwT);
    cudaGetSymbolAddress((void**)&w1h,  g_w1);
    cudaGetSymbolAddress((void**)&w2h,  g_w2);
    cudaGetSymbolAddress((void**)&wqkvh, g_wqkv);
    cudaGetSymbolAddress((void**)&wqkvl, g_wqkvl);
    cudaGetSymbolAddress((void**)&woh,  g_wo);
    cudaGetSymbolAddress((void**)&wol,  g_wol);

    cudaFuncSetAttribute(mma_gemm1<2>,  cudaFuncAttributeMaxDynamicSharedMemorySize, MM_SMEM1);
    cudaFuncSetAttribute(mma_gemm1<9>,  cudaFuncAttributeMaxDynamicSharedMemorySize, MM_SMEM1);
    cudaFuncSetAttribute(mma_gemm1<10>, cudaFuncAttributeMaxDynamicSharedMemorySize, MM_SMEM1);
    cudaFuncSetAttribute(mma_gemm1s<8>, cudaFuncAttributeMaxDynamicSharedMemorySize, MM_SMEM1N);
    cudaFuncSetAttribute(mma_gemm3<2>, cudaFuncAttributeMaxDynamicSharedMemorySize, MM_SMEM3);
    cudaFuncSetAttribute(mma_gemm3<6>, cudaFuncAttributeMaxDynamicSharedMemorySize, MM_SMEM3);
    cudaFuncSetAttribute(mma_gemm3sc<5>, cudaFuncAttributeMaxDynamicSharedMemorySize, MM_SMEM3S);

    dim3 blk(256);

    // 0) prep (fused: weight cvt/splits, bqkv, pwn zero, dwn)
    wprep_k<<<dim3(256, 8), blk>>>(Wq, Wk, Wv, Wo, w1_w, w2_w, bq, bk, bv, d_w,
                                   wqkvh, wqkvl, woh, wol, w1h, w2h, bqkv, pwn, dwn);
    cvtT_k<<<dim3(32, 32, cB), blk>>>(p_w, pwT, pwn);
    cvt_split_h<<<(cNT * cD) / 1024, blk>>>(x, xh, xl, (long)cNT * cD);

    // 1) fused qkv projection (split out, 3-product): [16384,256] @ [384,256]^T
    mma_gemm3<6><<<dim3(3, cNT / 128, 1), blk, MM_SMEM3>>>(
        xh, xl, wqkvh, wqkvl, nullptr, qkvh, qkvl, cD, cD, cD, 384, 384, 1,
        0, 0, 0, 0, 0, 0, 0, 0, bqkv, nullptr);

    // 2) v -> vT (fp16 single, compact 64 rows per (b,h))
    vT_k<<<dim3(32, 4, cB), blk>>>(qkvh, vTh);

    // 3) scores = q k^T / 8  [3-product, nk=1 -> 1-stage smem, occ 2]
    mma_gemm3sc<5><<<dim3(8, 8, 32), blk, MM_SMEM3S>>>(
        qkvh, qkvl, qkvh + 128, qkvl + 128, attn, cDK, 384, 384, cT, 1024, 2,
        (long)cT * 384, 64, (long)cT * 384, 64, 2 * cTT, cTT);

    // 4) masked softmax (writes final attn + fp16 single)
    softmax_k<<<dim3(cT, cH, cB), blk>>>(attn, smask, atth);

    // 5) ctx = attn @ v  [1-product, BN=64] -> exact fp16 split of fp32 result
    mma_gemm1s<8><<<dim3(1, 8, 32), blk, MM_SMEM1N>>>(
        atth, vTh, ctxh, ctxl, cT, cT, cT, 128, 64, 2,
        2 * cTT, cTT, (long)128 * cT, (long)64 * cT, (long)cT * 128, 64);

    // 6) apre = ctx @ Wo^T + bo + x  [3-product]
    mma_gemm3<2><<<dim3(2, cNT / 128, 1), blk, MM_SMEM3>>>(
        ctxh, ctxl, woh, wol, apre, nullptr, nullptr, 128, 128, 128, cD, 256, 1,
        0, 0, 0, 0, 0, 0, 0, 0, bo, x);

    // 7) a = LN(apre), masked; emit fp16 single  [warp-per-token]
    ln_k<<<cNT / 8, blk>>>(apre, g0, b0, mask, a, ah);

    // 8) h = mish(a @ w1^T + w1_b) -> fp16 single  [1-product, 3-stage, occ 2]
    mma_gemm1<9><<<dim3(cC / 128, cNT / 128, 1), blk, MM_SMEM1>>>(
        ah, w1h, nullptr, hh, cD, cD, cD, cC, 1024, 1,
        0, 0, 0, 0, 0, 0, 0, 0, w1_b, nullptr);

    // 9) tiled depthwise conv (fp16 in/out)
    conv2_k<<<dim3(cT / CV_TR, cC / 256, cB), blk>>>(hh, d_w, d_g, d_b, p_g, dwn, deph);

    // 10) pt = (dep @ pwT) * invnorm(pwnsum[o]) + p_b -> fp16 single  [1-prod, batched]
    mma_gemm1<10><<<dim3(cC / 128, cT / 128, cB), blk, MM_SMEM1>>>(
        deph, pwT, nullptr, pth, cC, cC, cC, cC, 1024, 1,
        (long)cT * cC, 0, (long)cC * cC, 0, (long)cT * cC, 0, cC, cC, p_b, pwn);

    // 11) o2 = pt @ w2^T + w2_b + a  [1-product]
    mma_gemm1<2><<<dim3(cD / 128, cNT / 128, 1), blk, MM_SMEM1>>>(
        pth, w2h, o2, nullptr, cC, cC, cC, cD, 256, 1,
        0, 0, 0, 0, 0, 0, 0, 0, w2_b, a);

    // 12) out = LN(o2), masked  [warp-per-token]
    ln_k<<<cNT / 8, blk>>>(o2, g1, b1, mask, out, nullptr);
}

// round 17
// speedup vs baseline: 1.0635x; 1.0013x over previous
#include <cuda_runtime.h>
#include <cuda_fp16.h>
#include <cstdint>
#include <math.h>

// ---------------- problem constants ----------------
constexpr int cB = 16, cT = 1024, cD = 256, cH = 2, cDK = 64, cC = 1024;
constexpr int cNT = cB * cT;            // 16384 tokens
constexpr long cTT = (long)cT * cT;     // 1M
constexpr float LN_EPS = 1e-5f;

// ---------------- device scratch (no allocs allowed) ----------------
__device__ float g_apre[cNT * cD];
__device__ float g_a   [cNT * cD];
__device__ float g_o2 [cNT * cD];
__device__ float g_dwn[cB * 9];
__device__ float g_pwn[cB * cC];        // sum of squares (atomic); inv-norm applied inline in pt epilogue
__device__ float g_bqkv[384];
// fp16 buffers
__device__ __half g_xh  [cNT * cD];
__device__ __half g_xl  [cNT * cD];
__device__ __half g_qkvh[cNT * 384];
__device__ __half g_qkvl[cNT * 384];
__device__ __half g_vTh [(long)cB * cH * 64 * cT];    // compact 64 rows per (b,h)
__device__ __half g_atth[(long)cB * cH * cTT];
__device__ __half g_ctxh[cNT * 128];
__device__ __half g_ctxl[cNT * 128];
__device__ __half g_ah  [cNT * cD];
__device__ __half g_hh  [cNT * cC];
__device__ __half g_deph[cNT * cC];
__device__ __half g_pth [cNT * cC];
__device__ __half g_pwT [(long)cB * cC * cC];
__device__ __half g_w1  [cC * cD];
__device__ __half g_w2  [cD * cC];
__device__ __half g_wqkv [384 * cD];
__device__ __half g_wqkvl[384 * cD];
__device__ __half g_wo  [cD * 128];
__device__ __half g_wol [cD * 128];

// ---------------- helpers ----------------
__device__ __forceinline__ uint32_t smem_u32(const void* p) {
    uint32_t a;
    asm("{ .reg .u64 t; cvta.to.shared.u64 t, %1; cvt.u32.u64 %0, t; }" : "=r"(a) : "l"(p));
    return a;
}
#define SW128(off) ((off) ^ (((off) >> 3) & 0x70))

__device__ __forceinline__ void split_h(float v, __half& h, __half& l) {
    h = __float2half_rn(v);
    l = __float2half_rn(v - __half2float(h));
}

__device__ __forceinline__ void ldsm4(uint32_t* r, uint32_t addr) {
    asm volatile("ldmatrix.sync.aligned.m8n8.x4.shared.b16 {%0,%1,%2,%3}, [%4];"
        : "=r"(r[0]), "=r"(r[1]), "=r"(r[2]), "=r"(r[3]) : "r"(addr));
}
__device__ __forceinline__ void mma16816(float* d, const uint32_t* a, const uint32_t* b) {
    asm volatile("mma.sync.aligned.m16n8k16.row.col.f32.f16.f16.f32 "
        "{%0,%1,%2,%3}, {%4,%5,%6,%7}, {%8,%9}, {%0,%1,%2,%3};"
        : "+f"(d[0]), "+f"(d[1]), "+f"(d[2]), "+f"(d[3])
        : "r"(a[0]), "r"(a[1]), "r"(a[2]), "r"(a[3]), "r"(b[0]), "r"(b[1]));
}
__device__ __forceinline__ void cp16(uint32_t saddr, const void* gptr) {
    asm volatile("cp.async.cg.shared.global [%0], [%1], 16;"
        :: "r"(saddr), "l"(__cvta_generic_to_global(gptr)));
}
__device__ __forceinline__ void cp_commit() {
    asm volatile("cp.async.commit_group;");
}
template<int N>
__device__ __forceinline__ void cp_wait() {
    asm volatile("cp.async.wait_group %0;" :: "n"(N));
}

__device__ __forceinline__ float warpReduceSum(float v) {
#pragma unroll
    for (int o = 16; o > 0; o >>= 1) v += __shfl_xor_sync(0xffffffffu, v, o);
    return v;
}
__device__ __forceinline__ float warpReduceMax(float v) {
#pragma unroll
    for (int o = 16; o > 0; o >>= 1) v = fmaxf(v, __shfl_xor_sync(0xffffffffu, v, o));
    return v;
}

// ---------------- mma.sync fp16 GEMM body (R14 pipeline structure) ----------------
// D[M,N] = A[M,K] @ B[N,K]^T.  Tile 128 x BN (BN=128 or 64), BK=64.
// NPROD=1: A,B single fp16 (3-stage).  NPROD=3: A and B split (2-stage).
// EPI: 2 = +bias[n]+aux residual -> f32 | 5 = acc*0.125 -> f32
//      6 = +bias -> fp16 split | 8 = raw -> fp16 split
//      9 = mish(acc+bias) -> fp16 single
//      10 = acc * invnorm(aux[n]) + bias[n] -> fp16 single (aux = raw sum of squares)
constexpr int MM_SMEM1  = 3 * 32768 + 1024;            // 1-prod, BN=128, 3 stages
constexpr int MM_SMEM1N = 3 * 24576 + 1024;            // 1-prod, BN=64,  3 stages
constexpr int MM_SMEM3  = 2 * 65536 + 1024;            // 3-prod, BN=128, 2 stages
constexpr int MM_SMEM3S = 1 * 65536 + 1024;            // 3-prod, BN=128, nk=1 (scores)

template<int EPI, int NPROD, int BN>
__device__ __forceinline__ void mma_body(
    const __half* __restrict__ Ah, const __half* __restrict__ Al,
    const __half* __restrict__ Bh, const __half* __restrict__ Bl,
    float* __restrict__ C, __half* __restrict__ Ch, __half* __restrict__ Cl,
    int Kd, int lda, int ldb, int ldc, int nLim, int zdiv,
    long aQ, long aR, long bQ, long bR, long cQ, long cR,
    long biasZ, long auxZ,
    const float* __restrict__ bias, const float* __restrict__ aux)
{
    constexpr int ASZ  = 16384;            // 128 rows x 64 cols fp16
    constexpr int BSZ  = BN * 128;
    constexpr int NAt  = (NPROD >= 2) ? 2 : 1;
    constexpr int NBt  = (NPROD == 3) ? 2 : 1;
    constexpr int BOFF = NAt * ASZ;
    constexpr int STAGE = NAt * ASZ + NBt * BSZ;
    constexpr int NSTG  = (NPROD == 1) ? 3 : 2;
    constexpr int NBT   = BN / 32;         // 16-col subtiles per warp-half (4 or 2)
    extern __shared__ char sm_raw[];
    uint32_t sb0 = smem_u32(sm_raw);
    uint32_t sb  = (sb0 + 1023u) & ~1023u;

    int z = blockIdx.z;
    int zq = z / zdiv, zr = z - zq * zdiv;
    long aoff = (long)zq * aQ + (long)zr * aR;
    long boff = (long)zq * bQ + (long)zr * bR;
    long coff = (long)zq * cQ + (long)zr * cR;
    Ah += aoff;
    if (NPROD >= 2) Al += aoff;
    Bh += boff;
    if (NPROD == 3) Bl += boff;
    if (C)  C  += coff;
    if (Ch) Ch += coff;
    if (Cl) Cl += coff;
    const float* biasp = bias ? bias + (long)zq * biasZ : nullptr;
    const float* auxp  = aux  ? aux  + (long)zq * auxZ  : nullptr;

    int m0 = blockIdx.y * 128, n0 = blockIdx.x * BN;
    int tid = threadIdx.x, wid = tid >> 5, lane = tid & 31;
    int wm = wid & 3, wn = wid >> 2;

    int lrow = tid >> 3, lcq = tid & 7;

    auto issue_stage = [&](int k0, uint32_t sbase) {
#pragma unroll
        for (int ti = 0; ti < 4; ti++) {
            int row = lrow + ti * 32;
            uint32_t soff = SW128((uint32_t)(row * 128 + lcq * 16));
            long ga = (long)(m0 + row) * lda + k0 + lcq * 8;
            cp16(sbase + soff, Ah + ga);
            if (NPROD >= 2) cp16(sbase + ASZ + soff, Al + ga);
        }
#pragma unroll
        for (int ti = 0; ti < BN / 32; ti++) {
            int row = lrow + ti * 32;
            uint32_t soff = SW128((uint32_t)(row * 128 + lcq * 16));
            long gb = (long)(n0 + row) * ldb + k0 + lcq * 8;
            cp16(sbase + BOFF + soff, Bh + gb);
            if (NPROD == 3) cp16(sbase + BOFF + BSZ + soff, Bl + gb);
        }
        cp_commit();
    };

    float acc[2][BN / 16][4];
#pragma unroll
    for (int i = 0; i < 2; i++)
#pragma unroll
        for (int j = 0; j < BN / 16; j++)
#pragma unroll
            for (int l = 0; l < 4; l++) acc[i][j][l] = 0.f;

    int nk = Kd >> 6;
#pragma unroll
    for (int s = 0; s < NSTG - 1; s++)
        if (s < nk) issue_stage(s << 6, sb + (uint32_t)s * STAGE);

    for (int i = 0; i < nk; i++) {
        uint32_t cur = sb + (uint32_t)(i % NSTG) * STAGE;
        int j = i + NSTG - 1;
        if (j < nk) issue_stage(j << 6, sb + (uint32_t)(j % NSTG) * STAGE);
        int rem = nk - 1 - i;
        if (NSTG == 3) {
            if (rem >= 2) cp_wait<2>();
            else if (rem == 1) cp_wait<1>();
            else cp_wait<0>();
        } else {
            if (rem >= 1) cp_wait<1>();
            else cp_wait<0>();
        }
        __syncthreads();

        uint32_t uAh = cur, uAl = cur + ASZ, uBh = cur + BOFF, uBl = cur + BOFF + BSZ;
#pragma unroll
        for (int ks = 0; ks < 4; ks++) {
            uint32_t afh[2][4], afl[2][4], bfh[NBT][4], bfl[NBT][4];
#pragma unroll
            for (int mt = 0; mt < 2; mt++) {
                int r = wm * 32 + mt * 16 + (lane & 15);
                int kc = ks * 2 + (lane >> 4);
                uint32_t off = SW128((uint32_t)(r * 128 + kc * 16));
                ldsm4(afh[mt], uAh + off);
                if (NPROD >= 2) ldsm4(afl[mt], uAl + off);
            }
#pragma unroll
            for (int bt = 0; bt < NBT; bt++) {
                int r = wn * (BN / 2) + bt * 16 + (lane & 7) + ((lane >> 4) << 3);
                int kc = ks * 2 + ((lane >> 3) & 1);
                uint32_t off = SW128((uint32_t)(r * 128 + kc * 16));
                ldsm4(bfh[bt], uBh + off);
                if (NPROD == 3) ldsm4(bfl[bt], uBl + off);
            }
#pragma unroll
            for (int p = 0; p < NPROD; p++)
#pragma unroll
                for (int mt = 0; mt < 2; mt++)
#pragma unroll
                    for (int bt = 0; bt < NBT; bt++)
#pragma unroll
                        for (int hh = 0; hh < 2; hh++) {
                            const uint32_t* af  = (p == 1) ? afl[mt] : afh[mt];
                            const uint32_t* bfp = (p == 2) ? &bfl[bt][hh * 2] : &bfh[bt][hh * 2];
                            mma16816(acc[mt][bt * 2 + hh], af, bfp);
                        }
        }
        __syncthreads();
    }

    // epilogue
#pragma unroll
    for (int mt = 0; mt < 2; mt++)
#pragma unroll
        for (int bt = 0; bt < NBT; bt++)
#pragma unroll
            for (int hh = 0; hh < 2; hh++) {
                float* d = acc[mt][bt * 2 + hh];
                int col = n0 + wn * (BN / 2) + bt * 16 + hh * 8 + (lane & 3) * 2;
                int r0  = m0 + wm * 32 + mt * 16 + (lane >> 2);
                if (col >= nLim) continue;
#pragma unroll
                for (int half = 0; half < 2; half++) {
                    int row = r0 + half * 8;
                    float t0 = d[half * 2 + 0], t1 = d[half * 2 + 1];
                    if (EPI == 2) {
                        t0 += biasp[col]     + auxp[(long)row * ldc + col];
                        t1 += biasp[col + 1] + auxp[(long)row * ldc + col + 1];
                        float2 v = {t0, t1};
                        *reinterpret_cast<float2*>(C + (long)row * ldc + col) = v;
                    } else if (EPI == 5) {
                        float2 v = {t0 * 0.125f, t1 * 0.125f};
                        *reinterpret_cast<float2*>(C + (long)row * ldc + col) = v;
                    } else if (EPI == 9) {
                        t0 += biasp[col];
                        t1 += biasp[col + 1];
                        float sp0 = (t0 > 20.f) ? t0 : log1pf(expf(t0));
                        float sp1 = (t1 > 20.f) ? t1 : log1pf(expf(t1));
                        t0 = t0 * tanhf(sp0);
                        t1 = t1 * tanhf(sp1);
                        __half2 hv = {__float2half_rn(t0), __float2half_rn(t1)};
                        *reinterpret_cast<__half2*>(Ch + (long)row * ldc + col) = hv;
                    } else if (EPI == 10) {
                        float inv0 = 1.f / fmaxf(sqrtf(auxp[col]),     1e-12f);
                        float inv1 = 1.f / fmaxf(sqrtf(auxp[col + 1]), 1e-12f);
                        t0 = t0 * inv0 + biasp[col];
                        t1 = t1 * inv1 + biasp[col + 1];
                        __half2 hv = {__float2half_rn(t0), __float2half_rn(t1)};
                        *reinterpret_cast<__half2*>(Ch + (long)row * ldc + col) = hv;
                    } else { // 6, 8: fp16 split outputs
                        if (EPI == 6) {
                            t0 += biasp[col];
                            t1 += biasp[col + 1];
                        }
                        __half h0, l0, h1, l1;
                        split_h(t0, h0, l0);
                        split_h(t1, h1, l1);
                        __half2 hv = {h0, h1}, lv = {l0, l1};
                        *reinterpret_cast<__half2*>(Ch + (long)row * ldc + col) = hv;
                        *reinterpret_cast<__half2*>(Cl + (long)row * ldc + col) = lv;
                    }
                }
            }
}

template<int EPI>
__global__ void __launch_bounds__(256, 2) mma_gemm1(
    const __half* __restrict__ Ah, const __half* __restrict__ Bh,
    float* __restrict__ C, __half* __restrict__ Ch,
    int Kd, int lda, int ldb, int ldc, int nLim, int zdiv,
    long aQ, long aR, long bQ, long bR, long cQ, long cR,
    long biasZ, long auxZ,
    const float* __restrict__ bias, const float* __restrict__ aux)
{
    mma_body<EPI, 1, 128>(Ah, nullptr, Bh, nullptr, C, Ch, nullptr, Kd, lda, ldb, ldc, nLim, zdiv,
                          aQ, aR, bQ, bR, cQ, cR, biasZ, auxZ, bias, aux);
}

// 1-product, BN=64, split fp16 output (for ctx)
template<int EPI>
__global__ void __launch_bounds__(256, 2) mma_gemm1s(
    const __half* __restrict__ Ah, const __half* __restrict__ Bh,
    __half* __restrict__ Ch, __half* __restrict__ Cl,
    int Kd, int lda, int ldb, int ldc, int nLim, int zdiv,
    long aQ, long aR, long bQ, long bR, long cQ, long cR)
{
    mma_body<EPI, 1, 64>(Ah, nullptr, Bh, nullptr, nullptr, Ch, Cl, Kd, lda, ldb, ldc, nLim, zdiv,
                         aQ, aR, bQ, bR, cQ, cR, 0, 0, nullptr, nullptr);
}

template<int EPI>
__global__ void __launch_bounds__(256) mma_gemm3(
    const __half* __restrict__ Ah, const __half* __restrict__ Al,
    const __half* __restrict__ Bh, const __half* __restrict__ Bl,
    float* __restrict__ C, __half* __restrict__ Ch, __half* __restrict__ Cl,
    int Kd, int lda, int ldb, int ldc, int nLim, int zdiv,
    long aQ, long aR, long bQ, long bR, long cQ, long cR,
    long biasZ, long auxZ,
    const float* __restrict__ bias, const float* __restrict__ aux)
{
    mma_body<EPI, 3, 128>(Ah, Al, Bh, Bl, C, Ch, Cl, Kd, lda, ldb, ldc, nLim, zdiv,
                          aQ, aR, bQ, bR, cQ, cR, biasZ, auxZ, bias, aux);
}

// scores-specific: reg-capped for 2 CTAs/SM, launched with 1-stage smem (nk=1)
template<int EPI>
__global__ void __launch_bounds__(256, 2) mma_gemm3sc(
    const __half* __restrict__ Ah, const __half* __restrict__ Al,
    const __half* __restrict__ Bh, const __half* __restrict__ Bl,
    float* __restrict__ C,
    int Kd, int lda, int ldb, int ldc, int nLim, int zdiv,
    long aQ, long aR, long bQ, long bR, long cQ, long cR)
{
    mma_body<EPI, 3, 128>(Ah, Al, Bh, Bl, C, nullptr, nullptr, Kd, lda, ldb, ldc, nLim, zdiv,
                          aQ, aR, bQ, bR, cQ, cR, 0, 0, nullptr, nullptr);
}

// ---------------- softmax (in place; emits fp16 single; vectorized) ----------------
__global__ void __launch_bounds__(256) softmax_k(float* __restrict__ attn,
                                                 const unsigned char* __restrict__ smask,
                                                 __half* __restrict__ ath)
{
    int i = blockIdx.x, h = blockIdx.y, b = blockIdx.z;
    long rbase = (((long)(b * cH + h)) * cT + i) * cT;
    float* row = attn + rbase;
    const unsigned char* mrow = smask + ((long)b * cT + i) * cT;
    int tid = threadIdx.x, lane = tid & 31, wid = tid >> 5;
    __shared__ float red[8];
    __shared__ float bc;

    float4 v4 = *reinterpret_cast<const float4*>(row + tid * 4);
    uchar4 m4 = *reinterpret_cast<const uchar4*>(mrow + tid * 4);
    float v[4] = {v4.x, v4.y, v4.z, v4.w};
    if (m4.x) v[0] = -1e9f;
    if (m4.y) v[1] = -1e9f;
    if (m4.z) v[2] = -1e9f;
    if (m4.w) v[3] = -1e9f;
    float mx = fmaxf(fmaxf(v[0], v[1]), fmaxf(v[2], v[3]));
    mx = warpReduceMax(mx);
    if (lane == 0) red[wid] = mx;
    __syncthreads();
    if (wid == 0) {
        float r = (lane < 8) ? red[lane] : -3.4e38f;
        r = warpReduceMax(r);
        if (lane == 0) bc = r;
    }
    __syncthreads();
    mx = bc;
    float sum = 0.f;
#pragma unroll
    for (int r = 0; r < 4; r++) { v[r] = expf(v[r] - mx); sum += v[r]; }
    __syncthreads();
    sum = warpReduceSum(sum);
    if (lane == 0) red[wid] = sum;
    __syncthreads();
    if (wid == 0) {
        float r = (lane < 8) ? red[lane] : 0.f;
        r = warpReduceSum(r);
        if (lane == 0) bc = r;
    }
    __syncthreads();
    float inv = 1.f / bc;
    float4 o = {v[0] * inv, v[1] * inv, v[2] * inv, v[3] * inv};
    *reinterpret_cast<float4*>(row + tid * 4) = o;
    __half2 h01 = {__float2half_rn(o.x), __float2half_rn(o.y)};
    __half2 h23 = {__float2half_rn(o.z), __float2half_rn(o.w)};
    *reinterpret_cast<__half2*>(ath + rbase + tid * 4)     = h01;
    *reinterpret_cast<__half2*>(ath + rbase + tid * 4 + 2) = h23;
}

// ---------------- LayerNorm: warp-per-token (8 tokens/CTA), no block sync ----------------
__global__ void __launch_bounds__(256) ln_k(const float* __restrict__ in,
                                            const float* __restrict__ g,
                                            const float* __restrict__ bta,
                                            const unsigned char* __restrict__ mask,
                                            float* __restrict__ out,
                                            __half* __restrict__ oh)
{
    int wid = threadIdx.x >> 5, lane = threadIdx.x & 31;
    long n = (long)blockIdx.x * 8 + wid;
    const float* src = in + n * cD + lane * 8;
    float4 a = *reinterpret_cast<const float4*>(src);
    float4 b = *reinterpret_cast<const float4*>(src + 4);
    float s  = (a.x + a.y) + (a.z + a.w) + (b.x + b.y) + (b.z + b.w);
    float s2 = (a.x * a.x + a.y * a.y) + (a.z * a.z + a.w * a.w)
             + (b.x * b.x + b.y * b.y) + (b.z * b.z + b.w * b.w);
    s  = warpReduceSum(s);
    s2 = warpReduceSum(s2);
    float mean = s * (1.f / cD);
    float var  = s2 * (1.f / cD) - mean * mean;
    float rstd = rsqrtf(var + LN_EPS);
    bool msk = mask[n];
    int c0 = lane * 8;
    const float4 g0 = *reinterpret_cast<const float4*>(g + c0);
    const float4 g1 = *reinterpret_cast<const float4*>(g + c0 + 4);
    const float4 t0 = *reinterpret_cast<const float4*>(bta + c0);
    const float4 t1 = *reinterpret_cast<const float4*>(bta + c0 + 4);
    float y[8];
    y[0] = (a.x - mean) * rstd * g0.x + t0.x;
    y[1] = (a.y - mean) * rstd * g0.y + t0.y;
    y[2] = (a.z - mean) * rstd * g0.z + t0.z;
    y[3] = (a.w - mean) * rstd * g0.w + t0.w;
    y[4] = (b.x - mean) * rstd * g1.x + t1.x;
    y[5] = (b.y - mean) * rstd * g1.y + t1.y;
    y[6] = (b.z - mean) * rstd * g1.z + t1.z;
    y[7] = (b.w - mean) * rstd * g1.w + t1.w;
    if (msk) {
#pragma unroll
        for (int j = 0; j < 8; j++) y[j] = 0.f;
    }
    float* dst = out + n * cD + c0;
    *reinterpret_cast<float4*>(dst)     = make_float4(y[0], y[1], y[2], y[3]);
    *reinterpret_cast<float4*>(dst + 4) = make_float4(y[4], y[5], y[6], y[7]);
    if (oh) {
        __half* hd = oh + n * cD + c0;
#pragma unroll
        for (int j = 0; j < 8; j += 2) {
            __half2 hv = {__float2half_rn(y[j]), __float2half_rn(y[j + 1])};
            *reinterpret_cast<__half2*>(hd + j) = hv;
        }
    }
}

// ---------------- fused small weight prep (one launch) ----------------
__device__ __forceinline__ void split4_at(const float* in, __half* oh, __half* ol, long i) {
    float4 v = *reinterpret_cast<const float4*>(in + i);
    __half h0, h1, h2, h3, l0, l1, l2, l3;
    split_h(v.x, h0, l0); split_h(v.y, h1, l1);
    split_h(v.z, h2, l2); split_h(v.w, h3, l3);
    __half2 ha = {h0, h1}, hb = {h2, h3}, la = {l0, l1}, lb = {l2, l3};
    *reinterpret_cast<__half2*>(oh + i)     = ha;
    *reinterpret_cast<__half2*>(oh + i + 2) = hb;
    *reinterpret_cast<__half2*>(ol + i)     = la;
    *reinterpret_cast<__half2*>(ol + i + 2) = lb;
}
__device__ __forceinline__ void cvt4_at(const float* in, __half* o, long i) {
    float4 v = *reinterpret_cast<const float4*>(in + i);
    __half2 a = {__float2half_rn(v.x), __float2half_rn(v.y)};
    __half2 b = {__float2half_rn(v.z), __float2half_rn(v.w)};
    *reinterpret_cast<__half2*>(o + i)     = a;
    *reinterpret_cast<__half2*>(o + i + 2) = b;
}

__global__ void __launch_bounds__(256) wprep_k(
    const float* __restrict__ Wq, const float* __restrict__ Wk,
    const float* __restrict__ Wv, const float* __restrict__ Wo,
    const float* __restrict__ w1, const float* __restrict__ w2,
    const float* __restrict__ bq, const float* __restrict__ bk,
    const float* __restrict__ bv,
    const float* __restrict__ d_w,
    __half* __restrict__ wqkvh, __half* __restrict__ wqkvl,
    __half* __restrict__ woh, __half* __restrict__ wol,
    __half* __restrict__ w1h, __half* __restrict__ w2h,
    float* __restrict__ bqkv, float* __restrict__ pwnsum,
    float* __restrict__ dwn)
{
    int task = blockIdx.y;
    long i = ((long)blockIdx.x * 256 + threadIdx.x) * 4;
    constexpr long SZp = (long)128 * cD;  // 32768
    constexpr long SZw = (long)cC * cD;   // 262144
    if (task == 0) { if (i < SZp) split4_at(Wq, wqkvh, wqkvl, i); }
    else if (task == 1) { if (i < SZp) split4_at(Wk, wqkvh + SZp, wqkvl + SZp, i); }
    else if (task == 2) { if (i < SZp) split4_at(Wv, wqkvh + 2 * SZp, wqkvl + 2 * SZp, i); }
    else if (task == 3) { if (i < SZp) split4_at(Wo, woh, wol, i); }
    else if (task == 4) { if (i < SZw) cvt4_at(w1, w1h, i); }
    else if (task == 5) { if (i < SZw) cvt4_at(w2, w2h, i); }
    else if (task == 6) {
        long t = (long)blockIdx.x * 256 + threadIdx.x;
        if (t < 128) bqkv[t] = bq[t];
        else if (t < 256) bqkv[t] = bk[t - 128];
        else if (t < 384) bqkv[t] = bv[t - 256];
        if (t < (long)cB * cC) pwnsum[t] = 0.f;
    } else { // 7: per-b depthwise weight inverse norms
        int b = blockIdx.x;
        if (b >= cB) return;
        int tid = threadIdx.x, lane = tid & 31;
        __shared__ float red9[9];
        if (tid < 9) red9[tid] = 0.f;
        __syncthreads();
        float s[9];
#pragma unroll
        for (int k = 0; k < 9; k++) s[k] = 0.f;
        for (int c = tid; c < cC; c += 256) {
            const float* wr = d_w + ((long)b * cC + c) * 9;
#pragma unroll
            for (int k = 0; k < 9; k++) { float w = wr[k]; s[k] += w * w; }
        }
#pragma unroll
        for (int k = 0; k < 9; k++) {
            float r = warpReduceSum(s[k]);
            if (lane == 0) atomicAdd(&red9[k], r);
        }
        __syncthreads();
        if (tid < 9)
            dwn[b * 9 + tid] = 1.f / fmaxf(sqrtf(red9[tid]), 1e-12f);
    }
}

// ---------------- fp32 -> fp16 hi/lo split (x) ----------------
__global__ void __launch_bounds__(256) cvt_split_h(const float* __restrict__ in,
                                                   __half* __restrict__ oh,
                                                   __half* __restrict__ ol, long n)
{
    long i = ((long)blockIdx.x * 256 + threadIdx.x) * 4;
    if (i >= n) return;
    split4_at(in, oh, ol, i);
}

// ---------------- qkv cols 256..383 (v) -> vT [(b,h)][n(64)][t] fp16 single ----------------
__global__ void __launch_bounds__(256) vT_k(const __half* __restrict__ qkvh,
                                            __half* __restrict__ vTh)
{
    __shared__ __half th[32][33];
    int b = blockIdx.z;
    int t0 = blockIdx.x * 32, c0 = blockIdx.y * 32;
    int tx = threadIdx.x & 31, ty = threadIdx.x >> 5;  // 32 x 8
#pragma unroll
    for (int i = 0; i < 4; i++) {
        int t = t0 + ty + i * 8;
        th[ty + i * 8][tx] = qkvh[((long)b * cT + t) * 384 + 256 + c0 + tx];
    }
    __syncthreads();
#pragma unroll
    for (int i = 0; i < 4; i++) {
        int c = c0 + ty + i * 8;
        int h = c >> 6, n = c & 63;
        vTh[((long)((b << 1) | h) * 64 + n) * cT + t0 + tx] = th[tx][ty + i * 8];
    }
}

// ---------------- p_w transpose to fp16 + fused pwn column sums ----------------
__global__ void __launch_bounds__(256) cvtT_k(const float* __restrict__ in,
                                              __half* __restrict__ oT,
                                              float* __restrict__ pwnsum)
{
    __shared__ float tile[32][33];
    __shared__ float colsum[32];
    int b = blockIdx.z;
    int o0 = blockIdx.x * 32, c0 = blockIdx.y * 32;
    int tx = threadIdx.x & 31, ty = threadIdx.x >> 5;  // 32 x 8
    const float* src = in + (long)b * cC * cC;
    if (threadIdx.x < 32) colsum[threadIdx.x] = 0.f;
    float s = 0.f;
#pragma unroll
    for (int i = 0; i < 4; i++) {
        int c = c0 + ty + i * 8;
        float v = src[(long)c * cC + o0 + tx];
        tile[ty + i * 8][tx] = v;
        s += v * v;
    }
    __syncthreads();
    atomicAdd(&colsum[tx], s);
    __half* dst = oT + (long)b * cC * cC;
#pragma unroll
    for (int i = 0; i < 4; i++) {
        int o = o0 + ty + i * 8;
        dst[(long)o * cC + c0 + tx] = __float2half_rn(tile[tx][ty + i * 8]);
    }
    __syncthreads();
    if (ty == 0) atomicAdd(&pwnsum[(long)b * cC + o0 + tx], colsum[tx]);
}

// ---------------- tiled depthwise conv (K=9): fp16 in, fp16 out ----------------
constexpr int CV_TR = 32;   // output t-rows per block
__global__ void __launch_bounds__(256) conv2_k(const __half* __restrict__ h,
                                               const float* __restrict__ d_w,
                                               const float* __restrict__ d_g,
                                               const float* __restrict__ d_b,
                                               const float* __restrict__ p_g,
                                               const float* __restrict__ dwn,
                                               __half* __restrict__ deph)
{
    __shared__ __half hs[CV_TR + 8][256];
    __shared__ float ws[9];
    int t0 = blockIdx.x * CV_TR, c0 = blockIdx.y * 256, b = blockIdx.z;
    int tid = threadIdx.x;
    if (tid < 9) ws[tid] = dwn[b * 9 + tid];
    __syncthreads();

#pragma unroll
    for (int i = tid; i < (CV_TR + 8) * 32; i += 256) {
        int r = i >> 5, q8 = i & 31;
        int t = t0 + r - 4;
        uint4 v = make_uint4(0u, 0u, 0u, 0u);
        if (t >= 0 && t < cT)
            v = *reinterpret_cast<const uint4*>(h + ((long)b * cT + t) * cC + c0 + q8 * 8);
        *reinterpret_cast<uint4*>(&hs[r][q8 * 8]) = v;
    }

    int c = c0 + tid;
    long bc = (long)b * cC + c;
    const float* wrow = d_w + bc * 9;
    float w[9];
#pragma unroll
    for (int k = 0; k < 9; k++) w[k] = wrow[k] * ws[k];
    float dg = d_g[bc], db = d_b[bc], pg = p_g[bc];
    __syncthreads();

#pragma unroll 4
    for (int tt = 0; tt < CV_TR; tt++) {
        float acc = 0.f;
#pragma unroll
        for (int k = 0; k < 9; k++) acc += __half2float(hs[tt + k][tid]) * w[k];
        float val = (acc * dg + db) * pg;
        deph[((long)b * cT + t0 + tt) * cC + c] = __float2half_rn(val);
    }
}

// ---------------- launch ----------------
extern "C" void kernel_launch(void* const* d_in, const int* in_sizes, int n_in,
                              void* d_out, int out_size)
{
    const float* x    = (const float*)d_in[0];
    const float* d_w  = (const float*)d_in[1];
    const float* d_g  = (const float*)d_in[2];
    const float* d_b  = (const float*)d_in[3];
    const float* p_w  = (const float*)d_in[4];
    const float* p_g  = (const float*)d_in[5];
    const float* p_b  = (const float*)d_in[6];
    const unsigned char* mask  = (const unsigned char*)d_in[7];
    const unsigned char* smask = (const unsigned char*)d_in[8];
    const float* Wq = (const float*)d_in[9];
    const float* bq = (const float*)d_in[10];
    const float* Wk = (const float*)d_in[11];
    const float* bk = (const float*)d_in[12];
    const float* Wv = (const float*)d_in[13];
    const float* bv = (const float*)d_in[14];
    const float* Wo = (const float*)d_in[15];
    const float* bo = (const float*)d_in[16];
    const float* g0 = (const float*)d_in[17];
    const float* b0 = (const float*)d_in[18];
    const float* w1_w = (const float*)d_in[19];
    const float* w1_b = (const float*)d_in[20];
    const float* w2_w = (const float*)d_in[21];
    const float* w2_b = (const float*)d_in[22];
    const float* g1 = (const float*)d_in[23];
    const float* b1 = (const float*)d_in[24];

    float* out  = (float*)d_out;
    float* attn = out + (long)cNT * cD;   // output tuple: (out[B,T,D], attn[B,H,T,T])

    float *apre, *a, *o2, *dwn, *pwn, *bqkv;
    __half *xh, *xl, *qkvh, *qkvl, *vTh, *atth, *ctxh, *ctxl;
    __half *ah, *hh, *deph, *pth, *pwT, *w1h, *w2h;
    __half *wqkvh, *wqkvl, *woh, *wol;
    cudaGetSymbolAddress((void**)&apre, g_apre);
    cudaGetSymbolAddress((void**)&a,    g_a);
    cudaGetSymbolAddress((void**)&o2,   g_o2);
    cudaGetSymbolAddress((void**)&dwn,  g_dwn);
    cudaGetSymbolAddress((void**)&pwn,  g_pwn);
    cudaGetSymbolAddress((void**)&bqkv, g_bqkv);
    cudaGetSymbolAddress((void**)&xh,   g_xh);
    cudaGetSymbolAddress((void**)&xl,   g_xl);
    cudaGetSymbolAddress((void**)&qkvh, g_qkvh);
    cudaGetSymbolAddress((void**)&qkvl, g_qkvl);
    cudaGetSymbolAddress((void**)&vTh,  g_vTh);
    cudaGetSymbolAddress((void**)&atth, g_atth);
    cudaGetSymbolAddress((void**)&ctxh, g_ctxh);
    cudaGetSymbolAddress((void**)&ctxl, g_ctxl);
    cudaGetSymbolAddress((void**)&ah,   g_ah);
    cudaGetSymbolAddress((void**)&hh,   g_hh);
    cudaGetSymbolAddress((void**)&deph, g_deph);
    cudaGetSymbolAddress((void**)&pth,  g_pth);
    cudaGetSymbolAddress((void**)&pwT,  g_pwT);
    cudaGetSymbolAddress((void**)&w1h,  g_w1);
    cudaGetSymbolAddress((void**)&w2h,  g_w2);
    cudaGetSymbolAddress((void**)&wqkvh, g_wqkv);
    cudaGetSymbolAddress((void**)&wqkvl, g_wqkvl);
    cudaGetSymbolAddress((void**)&woh,  g_wo);
    cudaGetSymbolAddress((void**)&wol,  g_wol);

    cudaFuncSetAttribute(mma_gemm1<2>,  cudaFuncAttributeMaxDynamicSharedMemorySize, MM_SMEM1);
    cudaFuncSetAttribute(mma_gemm1<9>,  cudaFuncAttributeMaxDynamicSharedMemorySize, MM_SMEM1);
    cudaFuncSetAttribute(mma_gemm1<10>, cudaFuncAttributeMaxDynamicSharedMemorySize, MM_SMEM1);
    cudaFuncSetAttribute(mma_gemm1s<8>, cudaFuncAttributeMaxDynamicSharedMemorySize, MM_SMEM1N);
    cudaFuncSetAttribute(mma_gemm3<2>, cudaFuncAttributeMaxDynamicSharedMemorySize, MM_SMEM3);
    cudaFuncSetAttribute(mma_gemm3<6>, cudaFuncAttributeMaxDynamicSharedMemorySize, MM_SMEM3);
    cudaFuncSetAttribute(mma_gemm3sc<5>, cudaFuncAttributeMaxDynamicSharedMemorySize, MM_SMEM3S);

    // side stream + fork/join events (created once on the uncaptured correctness
    // call; reused identically every call — same captured work each time)
    static cudaStream_t s2 = nullptr;
    static cudaEvent_t evFork = nullptr, evPwT = nullptr, evQkv = nullptr, evVT = nullptr;
    if (!s2) {
        cudaStreamCreateWithFlags(&s2, cudaStreamNonBlocking);
        cudaEventCreateWithFlags(&evFork, cudaEventDisableTiming);
        cudaEventCreateWithFlags(&evPwT,  cudaEventDisableTiming);
        cudaEventCreateWithFlags(&evQkv,  cudaEventDisableTiming);
        cudaEventCreateWithFlags(&evVT,   cudaEventDisableTiming);
    }

    dim3 blk(256);

    // 0) prep on main stream (zeros pwn sums; produces all small weights)
    wprep_k<<<dim3(256, 8), blk>>>(Wq, Wk, Wv, Wo, w1_w, w2_w, bq, bk, bv, d_w,
                                   wqkvh, wqkvl, woh, wol, w1h, w2h, bqkv, pwn, dwn);
    // fork: cvtT (p_w transpose + pwn sums) runs on s2, joined before pt GEMM
    cudaEventRecord(evFork, 0);
    cudaStreamWaitEvent(s2, evFork, 0);
    cvtT_k<<<dim3(32, 32, cB), blk, 0, s2>>>(p_w, pwT, pwn);
    cudaEventRecord(evPwT, s2);

    cvt_split_h<<<(cNT * cD) / 1024, blk>>>(x, xh, xl, (long)cNT * cD);

    // 1) fused qkv projection (split out, 3-product): [16384,256] @ [384,256]^T
    mma_gemm3<6><<<dim3(3, cNT / 128, 1), blk, MM_SMEM3>>>(
        xh, xl, wqkvh, wqkvl, nullptr, qkvh, qkvl, cD, cD, cD, 384, 384, 1,
        0, 0, 0, 0, 0, 0, 0, 0, bqkv, nullptr);

    // 2) v -> vT on s2 (depends on qkv; needed only by ctx)
    cudaEventRecord(evQkv, 0);
    cudaStreamWaitEvent(s2, evQkv, 0);
    vT_k<<<dim3(32, 4, cB), blk, 0, s2>>>(qkvh, vTh);
    cudaEventRecord(evVT, s2);

    // 3) scores = q k^T / 8  [3-product, nk=1 -> 1-stage smem, occ 2]
    mma_gemm3sc<5><<<dim3(8, 8, 32), blk, MM_SMEM3S>>>(
        qkvh, qkvl, qkvh + 128, qkvl + 128, attn, cDK, 384, 384, cT, 1024, 2,
        (long)cT * 384, 64, (long)cT * 384, 64, 2 * cTT, cTT);

    // 4) masked softmax (writes final attn + fp16 single)
    softmax_k<<<dim3(cT, cH, cB), blk>>>(attn, smask, atth);

    // 5) ctx = attn @ v  [1-product, BN=64] -> exact fp16 split (join vT first)
    cudaStreamWaitEvent(0, evVT, 0);
    mma_gemm1s<8><<<dim3(1, 8, 32), blk, MM_SMEM1N>>>(
        atth, vTh, ctxh, ctxl, cT, cT, cT, 128, 64, 2,
        2 * cTT, cTT, (long)128 * cT, (long)64 * cT, (long)cT * 128, 64);

    // 6) apre = ctx @ Wo^T + bo + x  [3-product]
    mma_gemm3<2><<<dim3(2, cNT / 128, 1), blk, MM_SMEM3>>>(
        ctxh, ctxl, woh, wol, apre, nullptr, nullptr, 128, 128, 128, cD, 256, 1,
        0, 0, 0, 0, 0, 0, 0, 0, bo, x);

    // 7) a = LN(apre), masked; emit fp16 single  [warp-per-token]
    ln_k<<<cNT / 8, blk>>>(apre, g0, b0, mask, a, ah);

    // 8) h = mish(a @ w1^T + w1_b) -> fp16 single  [1-product, 3-stage, occ 2]
    mma_gemm1<9><<<dim3(cC / 128, cNT / 128, 1), blk, MM_SMEM1>>>(
        ah, w1h, nullptr, hh, cD, cD, cD, cC, 1024, 1,
        0, 0, 0, 0, 0, 0, 0, 0, w1_b, nullptr);

    // 9) tiled depthwise conv (fp16 in/out)
    conv2_k<<<dim3(cT / CV_TR, cC / 256, cB), blk>>>(hh, d_w, d_g, d_b, p_g, dwn, deph);

    // 10) pt = (dep @ pwT) * invnorm(pwnsum[o]) + p_b  [join cvtT first]
    cudaStreamWaitEvent(0, evPwT, 0);
    mma_gemm1<10><<<dim3(cC / 128, cT / 128, cB), blk, MM_SMEM1>>>(
        deph, pwT, nullptr, pth, cC, cC, cC, cC, 1024, 1,
        (long)cT * cC, 0, (long)cC * cC, 0, (long)cT * cC, 0, cC, cC, p_b, pwn);

    // 11) o2 = pt @ w2^T + w2_b + a  [1-product]
    mma_gemm1<2><<<dim3(cD / 128, cNT / 128, 1), blk, MM_SMEM1>>>(
        pth, w2h, o2, nullptr, cC, cC, cC, cD, 256, 1,
        0, 0, 0, 0, 0, 0, 0, 0, w2_b, a);

    // 12) out = LN(o2), masked  [warp-per-token]
    ln_k<<<cNT / 8, blk>>>(o2, g1, b1, mask, out, nullptr);
}